// round 1
// baseline (speedup 1.0000x reference)
#include <cuda_runtime.h>
#include <cuda_bf16.h>

#define N_NODES 100000
#define N_EDGES 600000
#define N_GRAPHS 5000
#define IN_DIM 11
#define HID 128
#define EDGE_DIM 3
#define N_REST 4
#define BN_EPS 1e-5f

// ------------------------- scratch (static device memory) -------------------------
__device__ float g_pre[(size_t)N_NODES * HID];   // aggregated pre-MLP (also holds 11-dim layer0 pre, pitch 11)
__device__ float g_mid[(size_t)N_NODES * HID];   // after GEMM1+relu
__device__ float g_tmp[(size_t)N_NODES * HID];   // GEMM2 output pre-BN
__device__ float g_hA[(size_t)N_NODES * HID];
__device__ float g_hB[(size_t)N_NODES * HID];

__device__ int g_deg[N_NODES];
__device__ int g_rowptr[N_NODES + 1];
__device__ int g_cursor[N_NODES + 1];
__device__ int g_scanTmp[N_NODES];
__device__ int g_bsum[128];
__device__ int g_eid[N_EDGES];
__device__ int g_gptr[N_GRAPHS + 1];

__device__ float g_stats[2 * HID];               // colsum, colsumsq
__device__ float g_pool[(size_t)N_GRAPHS * HID];
__device__ float g_z1[(size_t)N_GRAPHS * HID];
__device__ float g_z2[(size_t)N_GRAPHS * HID];

// ------------------------- CSR build -------------------------
__global__ void count_deg_k(const int* __restrict__ dst, int* __restrict__ deg) {
    int e = blockIdx.x * blockDim.x + threadIdx.x;
    if (e < N_EDGES) atomicAdd(&deg[dst[e]], 1);
}

__global__ void scan_block_k(const int* __restrict__ deg, int* __restrict__ partial,
                             int* __restrict__ bsum, int n) {
    __shared__ int s[1024];
    int i = blockIdx.x * 1024 + threadIdx.x;
    int v = (i < n) ? deg[i] : 0;
    s[threadIdx.x] = v;
    __syncthreads();
    for (int off = 1; off < 1024; off <<= 1) {
        int t = (threadIdx.x >= off) ? s[threadIdx.x - off] : 0;
        __syncthreads();
        s[threadIdx.x] += t;
        __syncthreads();
    }
    if (i < n) partial[i] = s[threadIdx.x];      // inclusive scan within block
    if (threadIdx.x == 1023) bsum[blockIdx.x] = s[1023];
}

__global__ void scan_bsum_k(int* __restrict__ bsum, int nb) {
    if (threadIdx.x == 0 && blockIdx.x == 0) {
        int r = 0;
        for (int b = 0; b < nb; b++) { int t = bsum[b]; bsum[b] = r; r += t; }
    }
}

__global__ void scan_finish_k(const int* __restrict__ partial, const int* __restrict__ bsum,
                              int* __restrict__ rowptr, int n) {
    int i = blockIdx.x * 1024 + threadIdx.x;
    if (i < n) rowptr[i + 1] = partial[i] + bsum[blockIdx.x];
    if (i == 0) rowptr[0] = 0;
}

__global__ void fill_csr_k(const int* __restrict__ dst, int* __restrict__ cursor,
                           int* __restrict__ eid) {
    int e = blockIdx.x * blockDim.x + threadIdx.x;
    if (e < N_EDGES) {
        int p = atomicAdd(&cursor[dst[e]], 1);
        eid[p] = e;
    }
}

// ------------------------- aggregation -------------------------
// out[n][d] = (1+eps)*h[n][d] + sum_{e: dst(e)=n} relu(h[src(e)][d] + ea(e)@ew + eb)[d]
// generic over D (pitch = D). blockDim.x >= D.
__global__ void aggregate_k(const float* __restrict__ h, const float* __restrict__ ea,
                            const float* __restrict__ ew, const float* __restrict__ eb,
                            const float* __restrict__ epsp,
                            const int* __restrict__ src, const int* __restrict__ rowptr,
                            const int* __restrict__ eidlist, float* __restrict__ out, int D) {
    int n = blockIdx.x;
    int d = threadIdx.x;
    if (d >= D) return;
    float w0 = ew[d], w1 = ew[D + d], w2 = ew[2 * D + d], b = eb[d];
    int s0 = rowptr[n], s1 = rowptr[n + 1];
    float acc = 0.f;
    for (int p = s0; p < s1; p++) {
        int e = eidlist[p];
        int s = src[e];
        float a0 = __ldg(ea + (size_t)e * 3);
        float a1 = __ldg(ea + (size_t)e * 3 + 1);
        float a2 = __ldg(ea + (size_t)e * 3 + 2);
        float m = h[(size_t)s * D + d] + a0 * w0 + a1 * w1 + a2 * w2 + b;
        acc += fmaxf(m, 0.f);
    }
    float eps = *epsp;
    out[(size_t)n * D + d] = (1.f + eps) * h[(size_t)n * D + d] + acc;
}

// ------------------------- GEMM: C[M,128] = act(A[M,K] @ W[K,128] + bias) -------------------------
#define BM 64
#define BN 128
#define BK 32
__global__ void gemm_k(const float* __restrict__ A, int M, int K,
                       const float* __restrict__ W, const float* __restrict__ bias,
                       float* __restrict__ C, int do_relu,
                       float* __restrict__ ssum, float* __restrict__ ssq) {
    __shared__ float As[BK][BM + 1];
    __shared__ float Ws[BK][BN];
    int tid = threadIdx.x;            // 256
    int tx = tid & 15;                // col group: cols tx*8 .. tx*8+7
    int ty = tid >> 4;                // row group: rows ty*4 .. ty*4+3
    int rowBase = blockIdx.x * BM;
    float acc[4][8];
    #pragma unroll
    for (int i = 0; i < 4; i++)
        #pragma unroll
        for (int j = 0; j < 8; j++) acc[i][j] = 0.f;

    for (int k0 = 0; k0 < K; k0 += BK) {
        // A tile: 64 rows x BK, coalesced on k, stored transposed
        #pragma unroll
        for (int l = tid; l < BM * BK; l += 256) {
            int r = l >> 5, k = l & 31;
            int gr = rowBase + r, gk = k0 + k;
            As[k][r] = (gr < M && gk < K) ? A[(size_t)gr * K + gk] : 0.f;
        }
        // W tile: BK x 128
        #pragma unroll
        for (int l = tid; l < BK * BN; l += 256) {
            int k = l >> 7, c = l & 127;
            int gk = k0 + k;
            Ws[k][c] = (gk < K) ? W[(size_t)gk * BN + c] : 0.f;
        }
        __syncthreads();
        #pragma unroll
        for (int kk = 0; kk < BK; kk++) {
            float a[4], b[8];
            #pragma unroll
            for (int i = 0; i < 4; i++) a[i] = As[kk][ty * 4 + i];
            #pragma unroll
            for (int j = 0; j < 8; j++) b[j] = Ws[kk][tx * 8 + j];
            #pragma unroll
            for (int i = 0; i < 4; i++)
                #pragma unroll
                for (int j = 0; j < 8; j++) acc[i][j] += a[i] * b[j];
        }
        __syncthreads();
    }

    __shared__ float sSum[BN];
    __shared__ float sSq[BN];
    if (ssum) {
        if (tid < BN) { sSum[tid] = 0.f; sSq[tid] = 0.f; }
        __syncthreads();
    }
    float colS[8], colQ[8];
    #pragma unroll
    for (int j = 0; j < 8; j++) { colS[j] = 0.f; colQ[j] = 0.f; }
    #pragma unroll
    for (int i = 0; i < 4; i++) {
        int gr = rowBase + ty * 4 + i;
        if (gr < M) {
            #pragma unroll
            for (int j = 0; j < 8; j++) {
                int c = tx * 8 + j;
                float v = acc[i][j] + (bias ? bias[c] : 0.f);
                if (do_relu) v = fmaxf(v, 0.f);
                C[(size_t)gr * BN + c] = v;
                colS[j] += v;
                colQ[j] += v * v;
            }
        }
    }
    if (ssum) {
        #pragma unroll
        for (int j = 0; j < 8; j++) {
            atomicAdd(&sSum[tx * 8 + j], colS[j]);
            atomicAdd(&sSq[tx * 8 + j], colQ[j]);
        }
        __syncthreads();
        if (tid < BN) {
            atomicAdd(&ssum[tid], sSum[tid]);
            atomicAdd(&ssq[tid], sSq[tid]);
        }
    }
}

// ------------------------- BN + relu + optional residual -------------------------
__global__ void bn_relu_res_k(const float* __restrict__ tmp, const float* __restrict__ stats,
                              const float* __restrict__ gamma, const float* __restrict__ beta,
                              const float* __restrict__ res, float* __restrict__ out, int n_rows) {
    size_t i = (size_t)blockIdx.x * blockDim.x + threadIdx.x;
    size_t total = (size_t)n_rows * HID;
    if (i >= total) return;
    int d = (int)(i & (HID - 1));
    float invN = 1.f / (float)n_rows;
    float mu = stats[d] * invN;
    float var = stats[HID + d] * invN - mu * mu;
    float v = (tmp[i] - mu) * rsqrtf(var + BN_EPS) * gamma[d] + beta[d];
    v = fmaxf(v, 0.f);
    if (res) v += res[i];
    out[i] = v;
}

// ------------------------- pooling -------------------------
__global__ void graph_ptr_k(const int* __restrict__ batch, int* __restrict__ gptr) {
    int g = blockIdx.x * blockDim.x + threadIdx.x;
    if (g > N_GRAPHS) return;
    int lo = 0, hi = N_NODES;
    while (lo < hi) {
        int mid = (lo + hi) >> 1;
        if (batch[mid] < g) lo = mid + 1; else hi = mid;
    }
    gptr[g] = lo;
}

__global__ void pool_k(const float* __restrict__ h, const int* __restrict__ gptr,
                       float* __restrict__ pooled) {
    int g = blockIdx.x;
    int d = threadIdx.x;
    int a = gptr[g], b = gptr[g + 1];
    float acc = 0.f;
    for (int n = a; n < b; n++) acc += h[(size_t)n * HID + d];
    int cnt = b - a;
    float c = (float)(cnt > 1 ? cnt : 1);
    pooled[(size_t)g * HID + d] = acc / c;
}

// ------------------------- head final dot -------------------------
__global__ void head_out_k(const float* __restrict__ z, const float* __restrict__ w,
                           const float* __restrict__ b, float* __restrict__ out) {
    int g = blockIdx.x;
    int t = threadIdx.x; // 128
    float v = z[(size_t)g * HID + t] * w[t];
    #pragma unroll
    for (int off = 16; off; off >>= 1) v += __shfl_down_sync(0xFFFFFFFFu, v, off);
    __shared__ float s[4];
    if ((t & 31) == 0) s[t >> 5] = v;
    __syncthreads();
    if (t == 0) out[g] = s[0] + s[1] + s[2] + s[3] + b[0];
}

// ------------------------- host -------------------------
static void* sym_addr(const void* sym) {
    void* p = nullptr;
    cudaGetSymbolAddress(&p, sym);
    return p;
}

extern "C" void kernel_launch(void* const* d_in, const int* in_sizes, int n_in,
                              void* d_out, int out_size) {
    const float* x        = (const float*)d_in[0];
    const float* edge_attr= (const float*)d_in[1];
    const float* e_w0     = (const float*)d_in[2];
    const float* e_b0     = (const float*)d_in[3];
    const float* w1_0     = (const float*)d_in[4];
    const float* b1_0     = (const float*)d_in[5];
    const float* w2_0     = (const float*)d_in[6];
    const float* b2_0     = (const float*)d_in[7];
    const float* gamma0   = (const float*)d_in[8];
    const float* beta0    = (const float*)d_in[9];
    const float* eps0     = (const float*)d_in[10];
    const float* e_w      = (const float*)d_in[11];
    const float* e_b      = (const float*)d_in[12];
    const float* w1       = (const float*)d_in[13];
    const float* b1       = (const float*)d_in[14];
    const float* w2       = (const float*)d_in[15];
    const float* b2       = (const float*)d_in[16];
    const float* gamma    = (const float*)d_in[17];
    const float* beta     = (const float*)d_in[18];
    const float* eps_r    = (const float*)d_in[19];
    const float* hw1      = (const float*)d_in[20];
    const float* hb1      = (const float*)d_in[21];
    const float* hw2      = (const float*)d_in[22];
    const float* hb2      = (const float*)d_in[23];
    const float* hw3      = (const float*)d_in[24];
    const float* hb3      = (const float*)d_in[25];
    const int*   edge_index = (const int*)d_in[26];
    const int*   batch    = (const int*)d_in[27];

    const int* src = edge_index;
    const int* dst = edge_index + N_EDGES;

    float* pre   = (float*)sym_addr(g_pre);
    float* mid   = (float*)sym_addr(g_mid);
    float* tmp   = (float*)sym_addr(g_tmp);
    float* hA    = (float*)sym_addr(g_hA);
    float* hB    = (float*)sym_addr(g_hB);
    int*   deg   = (int*)sym_addr(g_deg);
    int*   rowptr= (int*)sym_addr(g_rowptr);
    int*   cursor= (int*)sym_addr(g_cursor);
    int*   scanT = (int*)sym_addr(g_scanTmp);
    int*   bsum  = (int*)sym_addr(g_bsum);
    int*   eid   = (int*)sym_addr(g_eid);
    int*   gptr  = (int*)sym_addr(g_gptr);
    float* stats = (float*)sym_addr(g_stats);
    float* pool  = (float*)sym_addr(g_pool);
    float* z1    = (float*)sym_addr(g_z1);
    float* z2    = (float*)sym_addr(g_z2);
    float* out   = (float*)d_out;

    const int SCAN_BLOCKS = (N_NODES + 1023) / 1024;

    // ---- CSR build ----
    cudaMemsetAsync(deg, 0, N_NODES * sizeof(int), 0);
    count_deg_k<<<(N_EDGES + 255) / 256, 256>>>(dst, deg);
    scan_block_k<<<SCAN_BLOCKS, 1024>>>(deg, scanT, bsum, N_NODES);
    scan_bsum_k<<<1, 32>>>(bsum, SCAN_BLOCKS);
    scan_finish_k<<<SCAN_BLOCKS, 1024>>>(scanT, bsum, rowptr, N_NODES);
    cudaMemcpyAsync(cursor, rowptr, N_NODES * sizeof(int), cudaMemcpyDeviceToDevice, 0);
    fill_csr_k<<<(N_EDGES + 255) / 256, 256>>>(dst, cursor, eid);

    // ---- graph boundaries for pooling ----
    graph_ptr_k<<<(N_GRAPHS + 1 + 127) / 128, 128>>>(batch, gptr);

    const int GEMM_BLOCKS_N = (N_NODES + BM - 1) / BM;
    const int BN_BLOCKS = (int)(((size_t)N_NODES * HID + 255) / 256);

    // ---- layer 0: IN_DIM(11) -> HID ----
    aggregate_k<<<N_NODES, 32>>>(x, edge_attr, e_w0, e_b0, eps0, src, rowptr, eid, pre, IN_DIM);
    gemm_k<<<GEMM_BLOCKS_N, 256>>>(pre, N_NODES, IN_DIM, w1_0, b1_0, mid, 1, nullptr, nullptr);
    cudaMemsetAsync(stats, 0, 2 * HID * sizeof(float), 0);
    gemm_k<<<GEMM_BLOCKS_N, 256>>>(mid, N_NODES, HID, w2_0, b2_0, tmp, 0, stats, stats + HID);
    bn_relu_res_k<<<BN_BLOCKS, 256>>>(tmp, stats, gamma0, beta0, nullptr, hA, N_NODES);

    // ---- layers 1..4: HID -> HID with residual ----
    float* cur = hA;
    float* nxt = hB;
    for (int i = 0; i < N_REST; i++) {
        aggregate_k<<<N_NODES, HID>>>(cur, edge_attr, e_w + (size_t)i * 3 * HID, e_b + (size_t)i * HID,
                                      eps_r + i, src, rowptr, eid, pre, HID);
        gemm_k<<<GEMM_BLOCKS_N, 256>>>(pre, N_NODES, HID, w1 + (size_t)i * HID * HID,
                                       b1 + (size_t)i * HID, mid, 1, nullptr, nullptr);
        cudaMemsetAsync(stats, 0, 2 * HID * sizeof(float), 0);
        gemm_k<<<GEMM_BLOCKS_N, 256>>>(mid, N_NODES, HID, w2 + (size_t)i * HID * HID,
                                       b2 + (size_t)i * HID, tmp, 0, stats, stats + HID);
        bn_relu_res_k<<<BN_BLOCKS, 256>>>(tmp, stats, gamma + (size_t)i * HID,
                                          beta + (size_t)i * HID, cur, nxt, N_NODES);
        float* t = cur; cur = nxt; nxt = t;
    }

    // ---- pooling ----
    pool_k<<<N_GRAPHS, HID>>>(cur, gptr, pool);

    // ---- head ----
    const int GEMM_BLOCKS_G = (N_GRAPHS + BM - 1) / BM;
    gemm_k<<<GEMM_BLOCKS_G, 256>>>(pool, N_GRAPHS, HID, hw1, hb1, z1, 1, nullptr, nullptr);
    gemm_k<<<GEMM_BLOCKS_G, 256>>>(z1, N_GRAPHS, HID, hw2, hb2, z2, 1, nullptr, nullptr);
    head_out_k<<<N_GRAPHS, HID>>>(z2, hw3, hb3, out);
}

// round 3
// speedup vs baseline: 1.3442x; 1.3442x over previous
#include <cuda_runtime.h>
#include <cuda_bf16.h>
#include <cstdint>

#define N_NODES 100000
#define N_EDGES 600000
#define N_GRAPHS 5000
#define IN_DIM 11
#define HID 128
#define EDGE_DIM 3
#define N_REST 4
#define BN_EPS 1e-5f

// ======================= PTX helpers (baseline sm_80+ ISA only) =======================
__device__ __forceinline__ uint32_t smem_u32(const void* p) {
    uint32_t a;
    asm("{ .reg .u64 t; cvta.to.shared.u64 t, %1; cvt.u32.u64 %0, t; }" : "=r"(a) : "l"(p));
    return a;
}

#define LDSM_X4(r0, r1, r2, r3, addr)                                            \
    asm volatile("ldmatrix.sync.aligned.m8n8.x4.shared.b16 {%0,%1,%2,%3}, [%4];" \
                 : "=r"(r0), "=r"(r1), "=r"(r2), "=r"(r3) : "r"(addr))

#define LDSM_X4T(r0, r1, r2, r3, addr)                                                 \
    asm volatile("ldmatrix.sync.aligned.m8n8.x4.trans.shared.b16 {%0,%1,%2,%3}, [%4];" \
                 : "=r"(r0), "=r"(r1), "=r"(r2), "=r"(r3) : "r"(addr))

__device__ __forceinline__ void mma_bf16(float* c, const uint32_t* a, const uint32_t* b) {
    asm volatile(
        "mma.sync.aligned.m16n8k16.row.col.f32.bf16.bf16.f32 "
        "{%0,%1,%2,%3}, {%4,%5,%6,%7}, {%8,%9}, {%0,%1,%2,%3};"
        : "+f"(c[0]), "+f"(c[1]), "+f"(c[2]), "+f"(c[3])
        : "r"(a[0]), "r"(a[1]), "r"(a[2]), "r"(a[3]), "r"(b[0]), "r"(b[1]));
}

// ======================= scratch (static device memory) =======================
__device__ float g_pre[(size_t)N_NODES * HID];
__device__ float g_mid[(size_t)N_NODES * HID];
__device__ float g_tmp[(size_t)N_NODES * HID];
__device__ float g_hA[(size_t)N_NODES * HID];
__device__ float g_hB[(size_t)N_NODES * HID];

__device__ int g_deg[N_NODES];
__device__ int g_rowptr[N_NODES + 1];
__device__ int g_cursor[N_NODES + 1];
__device__ int g_scanTmp[N_NODES];
__device__ int g_bsum[128];
__device__ int g_eid[N_EDGES];
__device__ int g_gptr[N_GRAPHS + 1];

__device__ float g_stats[2 * HID];
__device__ float g_pool[(size_t)N_GRAPHS * HID];
__device__ float g_z1[(size_t)N_GRAPHS * HID];
__device__ float g_z2[(size_t)N_GRAPHS * HID];

// ======================= CSR build =======================
__global__ void count_deg_k(const int* __restrict__ dst, int* __restrict__ deg) {
    int e = blockIdx.x * blockDim.x + threadIdx.x;
    if (e < N_EDGES) atomicAdd(&deg[dst[e]], 1);
}
__global__ void scan_block_k(const int* __restrict__ deg, int* __restrict__ partial,
                             int* __restrict__ bsum, int n) {
    __shared__ int s[1024];
    int i = blockIdx.x * 1024 + threadIdx.x;
    int v = (i < n) ? deg[i] : 0;
    s[threadIdx.x] = v;
    __syncthreads();
    for (int off = 1; off < 1024; off <<= 1) {
        int t = (threadIdx.x >= off) ? s[threadIdx.x - off] : 0;
        __syncthreads();
        s[threadIdx.x] += t;
        __syncthreads();
    }
    if (i < n) partial[i] = s[threadIdx.x];
    if (threadIdx.x == 1023) bsum[blockIdx.x] = s[1023];
}
__global__ void scan_bsum_k(int* __restrict__ bsum, int nb) {
    if (threadIdx.x == 0 && blockIdx.x == 0) {
        int r = 0;
        for (int b = 0; b < nb; b++) { int t = bsum[b]; bsum[b] = r; r += t; }
    }
}
__global__ void scan_finish_k(const int* __restrict__ partial, const int* __restrict__ bsum,
                              int* __restrict__ rowptr, int n) {
    int i = blockIdx.x * 1024 + threadIdx.x;
    if (i < n) rowptr[i + 1] = partial[i] + bsum[blockIdx.x];
    if (i == 0) rowptr[0] = 0;
}
__global__ void fill_csr_k(const int* __restrict__ dst, int* __restrict__ cursor,
                           int* __restrict__ eid) {
    int e = blockIdx.x * blockDim.x + threadIdx.x;
    if (e < N_EDGES) {
        int p = atomicAdd(&cursor[dst[e]], 1);
        eid[p] = e;
    }
}

// ======================= aggregation =======================
__global__ void aggregate_k(const float* __restrict__ h, const float* __restrict__ ea,
                            const float* __restrict__ ew, const float* __restrict__ eb,
                            const float* __restrict__ epsp,
                            const int* __restrict__ src, const int* __restrict__ rowptr,
                            const int* __restrict__ eidlist, float* __restrict__ out, int D) {
    int n = blockIdx.x;
    int d = threadIdx.x;
    if (d >= D) return;
    float w0 = ew[d], w1 = ew[D + d], w2 = ew[2 * D + d], b = eb[d];
    int s0 = rowptr[n], s1 = rowptr[n + 1];
    float acc = 0.f;
    for (int p = s0; p < s1; p++) {
        int e = eidlist[p];
        int s = src[e];
        float a0 = __ldg(ea + (size_t)e * 3);
        float a1 = __ldg(ea + (size_t)e * 3 + 1);
        float a2 = __ldg(ea + (size_t)e * 3 + 2);
        float m = h[(size_t)s * D + d] + a0 * w0 + a1 * w1 + a2 * w2 + b;
        acc += fmaxf(m, 0.f);
    }
    float eps = *epsp;
    out[(size_t)n * D + d] = (1.f + eps) * h[(size_t)n * D + d] + acc;
}

// ======================= HMMA tensor-core GEMM =======================
// C[M,128] = act(A[M,Kact](pitch Apitch) @ W[Kact,128] + bias)
// fp32 emulated via bf16 hi/lo split: 3 mma passes (hh, hl, lh) into fp32 accum.
// SMEM layout (bytes):
//   A_hi [128][136]bf16 @ 0       (34816)
//   A_lo                 @ 34816
//   W_hi [128][136]bf16 @ 69632   (row-major [k][n], padded)
//   W_lo                 @ 104448
//   bias                 @ 139264 (512)
//   stats                @ 139776 (2048)
#define SA_HI   0
#define SA_LO   34816
#define SW_HI   69632
#define SW_LO   104448
#define S_BIAS  139264
#define S_STAT  139776
#define SM_TOTAL (S_STAT + 2048)
#define APAD 136
#define STG_PITCH 130

__global__ void __launch_bounds__(256, 1)
gemm_mma_k(const float* __restrict__ A, int M, int Kact, int Apitch,
           const float* __restrict__ W, const float* __restrict__ bias,
           float* __restrict__ C, int do_relu,
           float* __restrict__ ssum, float* __restrict__ ssq, int nsteps) {
    extern __shared__ __align__(16) char smem[];
    __nv_bfloat16* aHi = (__nv_bfloat16*)(smem + SA_HI);
    __nv_bfloat16* aLo = (__nv_bfloat16*)(smem + SA_LO);
    __nv_bfloat16* wHi = (__nv_bfloat16*)(smem + SW_HI);
    __nv_bfloat16* wLo = (__nv_bfloat16*)(smem + SW_LO);
    float* biasS = (float*)(smem + S_BIAS);
    float* statS = (float*)(smem + S_STAT);

    int tid = threadIdx.x;
    int lane = tid & 31;
    int wid = tid >> 5;
    int rowBase = blockIdx.x * 128;
    int kmax = nsteps << 4;                 // 16 or 128
    int ks = (nsteps == 8) ? 7 : 4;
    int kmask = kmax - 1;

    if (tid < HID) biasS[tid] = bias[tid];

    // ---- load + split A [128 x kmax] ----
    for (int idx = tid; idx < 128 * kmax; idx += 256) {
        int r = idx >> ks, k = idx & kmask;
        int gr = rowBase + r;
        float a = (gr < M && k < Kact) ? __ldg(A + (size_t)gr * Apitch + k) : 0.f;
        __nv_bfloat16 h = __float2bfloat16(a);
        __nv_bfloat16 l = __float2bfloat16(a - __bfloat162float(h));
        aHi[r * APAD + k] = h;
        aLo[r * APAD + k] = l;
    }
    // ---- load + split W [kmax x 128] (row-major, coalesced both ways) ----
    for (int idx = tid; idx < kmax * 128; idx += 256) {
        int k = idx >> 7, n = idx & 127;
        float w = (k < Kact) ? __ldg(W + (size_t)k * HID + n) : 0.f;
        __nv_bfloat16 h = __float2bfloat16(w);
        __nv_bfloat16 l = __float2bfloat16(w - __bfloat162float(h));
        wHi[k * APAD + n] = h;
        wLo[k * APAD + n] = l;
    }
    __syncthreads();

    // ---- warp tiling: 8 warps = 4 (rows) x 2 (cols); warp tile 32 x 64 ----
    int warpR = (wid >> 1) << 5;
    int warpC = (wid & 1) << 6;
    float acc[2][8][4];
    #pragma unroll
    for (int m = 0; m < 2; m++)
        #pragma unroll
        for (int j = 0; j < 8; j++)
            #pragma unroll
            for (int q = 0; q < 4; q++) acc[m][j][q] = 0.f;

    uint32_t aBase = smem_u32(aHi);
    uint32_t wBase = smem_u32(wHi);

    for (int s = 0; s < nsteps; s++) {
        int k0 = s << 4;
        // A fragment addresses: row = warpR + (lane&15) [+16 per atom], col = k0 + (lane>>4)*8
        uint32_t aAddr = aBase +
            ((uint32_t)((warpR + (lane & 15)) * APAD + k0 + ((lane >> 4) << 3)) << 1);
        uint32_t ah0[4], ah1[4], al0[4], al1[4];
        LDSM_X4(ah0[0], ah0[1], ah0[2], ah0[3], aAddr);
        LDSM_X4(ah1[0], ah1[1], ah1[2], ah1[3], aAddr + 16 * APAD * 2);
        LDSM_X4(al0[0], al0[1], al0[2], al0[3], aAddr + (SA_LO - SA_HI));
        LDSM_X4(al1[0], al1[1], al1[2], al1[3], aAddr + (SA_LO - SA_HI) + 16 * APAD * 2);

        // B fragment addresses: k = k0 + (lane&7) + ((lane>>3)&1)*8, n = warpC + (lane>>4)*8 [+16 per pair]
        uint32_t bAddr = wBase +
            ((uint32_t)((k0 + (lane & 7) + ((lane >> 3) & 1) * 8) * APAD +
                        warpC + ((lane >> 4) << 3)) << 1);
        uint32_t bh[8][2], bl[8][2];
        #pragma unroll
        for (int p = 0; p < 4; p++) {
            uint32_t r0, r1, r2, r3;
            LDSM_X4T(r0, r1, r2, r3, bAddr + p * 32);
            bh[2 * p][0] = r0; bh[2 * p][1] = r1;
            bh[2 * p + 1][0] = r2; bh[2 * p + 1][1] = r3;
            LDSM_X4T(r0, r1, r2, r3, bAddr + (SW_LO - SW_HI) + p * 32);
            bl[2 * p][0] = r0; bl[2 * p][1] = r1;
            bl[2 * p + 1][0] = r2; bl[2 * p + 1][1] = r3;
        }

        #pragma unroll
        for (int j = 0; j < 8; j++) {
            mma_bf16(acc[0][j], ah0, bh[j]);
            mma_bf16(acc[1][j], ah1, bh[j]);
            mma_bf16(acc[0][j], ah0, bl[j]);
            mma_bf16(acc[1][j], ah1, bl[j]);
            mma_bf16(acc[0][j], al0, bh[j]);
            mma_bf16(acc[1][j], al1, bh[j]);
        }
    }
    __syncthreads();   // done reading A region; reuse as staging

    // ---- epilogue phase 1: accum -> staging smem [128][130] floats ----
    float* stg = (float*)smem;
    #pragma unroll
    for (int m = 0; m < 2; m++) {
        #pragma unroll
        for (int j = 0; j < 8; j++) {
            int row = warpR + m * 16 + (lane >> 2);
            int col = warpC + j * 8 + ((lane & 3) << 1);
            stg[row * STG_PITCH + col]     = acc[m][j][0];
            stg[row * STG_PITCH + col + 1] = acc[m][j][1];
            stg[(row + 8) * STG_PITCH + col]     = acc[m][j][2];
            stg[(row + 8) * STG_PITCH + col + 1] = acc[m][j][3];
        }
    }
    __syncthreads();

    // ---- epilogue phase 2: bias/relu + coalesced store + fused BN stats ----
    {
        int c = tid & 127, hh = tid >> 7;
        float bia = biasS[c];
        float s0 = 0.f, q0 = 0.f;
        #pragma unroll 4
        for (int j = 0; j < 64; j++) {
            int r = hh * 64 + j;
            int gr = rowBase + r;
            if (gr < M) {
                float v = stg[r * STG_PITCH + c] + bia;
                if (do_relu) v = fmaxf(v, 0.f);
                C[(size_t)gr * HID + c] = v;
                s0 += v;
                q0 += v * v;
            }
        }
        if (ssum) {
            statS[hh * 128 + c] = s0;
            statS[256 + hh * 128 + c] = q0;
            __syncthreads();
            if (tid < 128) {
                atomicAdd(&ssum[tid], statS[tid] + statS[128 + tid]);
                atomicAdd(&ssq[tid], statS[256 + tid] + statS[384 + tid]);
            }
        }
    }
}

// ======================= BN + relu + optional residual =======================
__global__ void bn_relu_res_k(const float* __restrict__ tmp, const float* __restrict__ stats,
                              const float* __restrict__ gamma, const float* __restrict__ beta,
                              const float* __restrict__ res, float* __restrict__ out, int n_rows) {
    size_t i = (size_t)blockIdx.x * blockDim.x + threadIdx.x;
    size_t total = (size_t)n_rows * HID;
    if (i >= total) return;
    int d = (int)(i & (HID - 1));
    float invN = 1.f / (float)n_rows;
    float mu = stats[d] * invN;
    float var = stats[HID + d] * invN - mu * mu;
    float v = (tmp[i] - mu) * rsqrtf(var + BN_EPS) * gamma[d] + beta[d];
    v = fmaxf(v, 0.f);
    if (res) v += res[i];
    out[i] = v;
}

// ======================= pooling =======================
__global__ void graph_ptr_k(const int* __restrict__ batch, int* __restrict__ gptr) {
    int g = blockIdx.x * blockDim.x + threadIdx.x;
    if (g > N_GRAPHS) return;
    int lo = 0, hi = N_NODES;
    while (lo < hi) {
        int mid = (lo + hi) >> 1;
        if (batch[mid] < g) lo = mid + 1; else hi = mid;
    }
    gptr[g] = lo;
}
__global__ void pool_k(const float* __restrict__ h, const int* __restrict__ gptr,
                       float* __restrict__ pooled) {
    int g = blockIdx.x;
    int d = threadIdx.x;
    int a = gptr[g], b = gptr[g + 1];
    float acc = 0.f;
    for (int n = a; n < b; n++) acc += h[(size_t)n * HID + d];
    int cnt = b - a;
    float c = (float)(cnt > 1 ? cnt : 1);
    pooled[(size_t)g * HID + d] = acc / c;
}

// ======================= head final dot =======================
__global__ void head_out_k(const float* __restrict__ z, const float* __restrict__ w,
                           const float* __restrict__ b, float* __restrict__ out) {
    int g = blockIdx.x;
    int t = threadIdx.x; // 128
    float v = z[(size_t)g * HID + t] * w[t];
    #pragma unroll
    for (int off = 16; off; off >>= 1) v += __shfl_down_sync(0xFFFFFFFFu, v, off);
    __shared__ float s[4];
    if ((t & 31) == 0) s[t >> 5] = v;
    __syncthreads();
    if (t == 0) out[g] = s[0] + s[1] + s[2] + s[3] + b[0];
}

// ======================= host =======================
static void* sym_addr(const void* sym) {
    void* p = nullptr;
    cudaGetSymbolAddress(&p, sym);
    return p;
}

extern "C" void kernel_launch(void* const* d_in, const int* in_sizes, int n_in,
                              void* d_out, int out_size) {
    const float* x        = (const float*)d_in[0];
    const float* edge_attr= (const float*)d_in[1];
    const float* e_w0     = (const float*)d_in[2];
    const float* e_b0     = (const float*)d_in[3];
    const float* w1_0     = (const float*)d_in[4];
    const float* b1_0     = (const float*)d_in[5];
    const float* w2_0     = (const float*)d_in[6];
    const float* b2_0     = (const float*)d_in[7];
    const float* gamma0   = (const float*)d_in[8];
    const float* beta0    = (const float*)d_in[9];
    const float* eps0     = (const float*)d_in[10];
    const float* e_w      = (const float*)d_in[11];
    const float* e_b      = (const float*)d_in[12];
    const float* w1       = (const float*)d_in[13];
    const float* b1       = (const float*)d_in[14];
    const float* w2       = (const float*)d_in[15];
    const float* b2       = (const float*)d_in[16];
    const float* gamma    = (const float*)d_in[17];
    const float* beta     = (const float*)d_in[18];
    const float* eps_r    = (const float*)d_in[19];
    const float* hw1      = (const float*)d_in[20];
    const float* hb1      = (const float*)d_in[21];
    const float* hw2      = (const float*)d_in[22];
    const float* hb2      = (const float*)d_in[23];
    const float* hw3      = (const float*)d_in[24];
    const float* hb3      = (const float*)d_in[25];
    const int*   edge_index = (const int*)d_in[26];
    const int*   batch    = (const int*)d_in[27];

    const int* src = edge_index;
    const int* dst = edge_index + N_EDGES;

    float* pre   = (float*)sym_addr(g_pre);
    float* mid   = (float*)sym_addr(g_mid);
    float* tmp   = (float*)sym_addr(g_tmp);
    float* hA    = (float*)sym_addr(g_hA);
    float* hB    = (float*)sym_addr(g_hB);
    int*   deg   = (int*)sym_addr(g_deg);
    int*   rowptr= (int*)sym_addr(g_rowptr);
    int*   cursor= (int*)sym_addr(g_cursor);
    int*   scanT = (int*)sym_addr(g_scanTmp);
    int*   bsum  = (int*)sym_addr(g_bsum);
    int*   eid   = (int*)sym_addr(g_eid);
    int*   gptr  = (int*)sym_addr(g_gptr);
    float* stats = (float*)sym_addr(g_stats);
    float* pool  = (float*)sym_addr(g_pool);
    float* z1    = (float*)sym_addr(g_z1);
    float* z2    = (float*)sym_addr(g_z2);
    float* out   = (float*)d_out;

    cudaFuncSetAttribute(gemm_mma_k, cudaFuncAttributeMaxDynamicSharedMemorySize, SM_TOTAL);

    const int SCAN_BLOCKS = (N_NODES + 1023) / 1024;

    // ---- CSR build ----
    cudaMemsetAsync(deg, 0, N_NODES * sizeof(int), 0);
    count_deg_k<<<(N_EDGES + 255) / 256, 256>>>(dst, deg);
    scan_block_k<<<SCAN_BLOCKS, 1024>>>(deg, scanT, bsum, N_NODES);
    scan_bsum_k<<<1, 32>>>(bsum, SCAN_BLOCKS);
    scan_finish_k<<<SCAN_BLOCKS, 1024>>>(scanT, bsum, rowptr, N_NODES);
    cudaMemcpyAsync(cursor, rowptr, N_NODES * sizeof(int), cudaMemcpyDeviceToDevice, 0);
    fill_csr_k<<<(N_EDGES + 255) / 256, 256>>>(dst, cursor, eid);

    // ---- graph boundaries ----
    graph_ptr_k<<<(N_GRAPHS + 1 + 127) / 128, 128>>>(batch, gptr);

    const int GB_N = (N_NODES + 127) / 128;
    const int GB_G = (N_GRAPHS + 127) / 128;
    const int BN_BLOCKS = (int)(((size_t)N_NODES * HID + 255) / 256);

    // ---- layer 0: IN_DIM(11) -> HID ----
    aggregate_k<<<N_NODES, 32>>>(x, edge_attr, e_w0, e_b0, eps0, src, rowptr, eid, pre, IN_DIM);
    gemm_mma_k<<<GB_N, 256, SM_TOTAL>>>(pre, N_NODES, IN_DIM, IN_DIM, w1_0, b1_0, mid, 1, nullptr, nullptr, 1);
    cudaMemsetAsync(stats, 0, 2 * HID * sizeof(float), 0);
    gemm_mma_k<<<GB_N, 256, SM_TOTAL>>>(mid, N_NODES, HID, HID, w2_0, b2_0, tmp, 0, stats, stats + HID, 8);
    bn_relu_res_k<<<BN_BLOCKS, 256>>>(tmp, stats, gamma0, beta0, nullptr, hA, N_NODES);

    // ---- layers 1..4 ----
    float* cur = hA;
    float* nxt = hB;
    for (int i = 0; i < N_REST; i++) {
        aggregate_k<<<N_NODES, HID>>>(cur, edge_attr, e_w + (size_t)i * 3 * HID, e_b + (size_t)i * HID,
                                      eps_r + i, src, rowptr, eid, pre, HID);
        gemm_mma_k<<<GB_N, 256, SM_TOTAL>>>(pre, N_NODES, HID, HID, w1 + (size_t)i * HID * HID,
                                            b1 + (size_t)i * HID, mid, 1, nullptr, nullptr, 8);
        cudaMemsetAsync(stats, 0, 2 * HID * sizeof(float), 0);
        gemm_mma_k<<<GB_N, 256, SM_TOTAL>>>(mid, N_NODES, HID, HID, w2 + (size_t)i * HID * HID,
                                            b2 + (size_t)i * HID, tmp, 0, stats, stats + HID, 8);
        bn_relu_res_k<<<BN_BLOCKS, 256>>>(tmp, stats, gamma + (size_t)i * HID,
                                          beta + (size_t)i * HID, cur, nxt, N_NODES);
        float* t = cur; cur = nxt; nxt = t;
    }

    // ---- pooling ----
    pool_k<<<N_GRAPHS, HID>>>(cur, gptr, pool);

    // ---- head ----
    gemm_mma_k<<<GB_G, 256, SM_TOTAL>>>(pool, N_GRAPHS, HID, HID, hw1, hb1, z1, 1, nullptr, nullptr, 8);
    gemm_mma_k<<<GB_G, 256, SM_TOTAL>>>(z1, N_GRAPHS, HID, HID, hw2, hb2, z2, 1, nullptr, nullptr, 8);
    head_out_k<<<N_GRAPHS, HID>>>(z2, hw3, hb3, out);
}

// round 4
// speedup vs baseline: 1.4112x; 1.0499x over previous
#include <cuda_runtime.h>
#include <cuda_bf16.h>
#include <cstdint>

#define N_NODES 100000
#define N_EDGES 600000
#define N_GRAPHS 5000
#define IN_DIM 11
#define HID 128
#define EDGE_DIM 3
#define N_REST 4
#define BN_EPS 1e-5f

// ======================= PTX helpers (baseline sm_80+ ISA only) =======================
__device__ __forceinline__ uint32_t smem_u32(const void* p) {
    uint32_t a;
    asm("{ .reg .u64 t; cvta.to.shared.u64 t, %1; cvt.u32.u64 %0, t; }" : "=r"(a) : "l"(p));
    return a;
}

#define LDSM_X4(r0, r1, r2, r3, addr)                                            \
    asm volatile("ldmatrix.sync.aligned.m8n8.x4.shared.b16 {%0,%1,%2,%3}, [%4];" \
                 : "=r"(r0), "=r"(r1), "=r"(r2), "=r"(r3) : "r"(addr))

#define LDSM_X4T(r0, r1, r2, r3, addr)                                                 \
    asm volatile("ldmatrix.sync.aligned.m8n8.x4.trans.shared.b16 {%0,%1,%2,%3}, [%4];" \
                 : "=r"(r0), "=r"(r1), "=r"(r2), "=r"(r3) : "r"(addr))

__device__ __forceinline__ void mma_bf16(float* c, const uint32_t* a, const uint32_t* b) {
    asm volatile(
        "mma.sync.aligned.m16n8k16.row.col.f32.bf16.bf16.f32 "
        "{%0,%1,%2,%3}, {%4,%5,%6,%7}, {%8,%9}, {%0,%1,%2,%3};"
        : "+f"(c[0]), "+f"(c[1]), "+f"(c[2]), "+f"(c[3])
        : "r"(a[0]), "r"(a[1]), "r"(a[2]), "r"(a[3]), "r"(b[0]), "r"(b[1]));
}

// ======================= scratch =======================
__device__ float g_pre[(size_t)N_NODES * HID];
__device__ float g_tmp[(size_t)N_NODES * HID];
__device__ float g_hA[(size_t)N_NODES * HID];
__device__ float g_hB[(size_t)N_NODES * HID];

__device__ int g_deg[N_NODES];
__device__ int g_rowptr[N_NODES + 1];
__device__ int g_cursor[N_NODES + 1];
__device__ int g_srcp[N_EDGES];
__device__ float4 g_eap[N_EDGES];
__device__ int g_gptr[N_GRAPHS + 1];

__device__ float g_stats[2 * HID];
__device__ float g_pool[(size_t)N_GRAPHS * HID];
__device__ float g_z2[(size_t)N_GRAPHS * HID];

// pre-split weights: 12 slots of [128][128] bf16 (slot0 = w1_0 zero-padded past row 10)
__device__ __nv_bfloat16 g_whi[12 * 128 * 128];
__device__ __nv_bfloat16 g_wlo[12 * 128 * 128];

// ======================= weight split =======================
__global__ void split_w_k(const float* __restrict__ w1_0, const float* __restrict__ w2_0,
                          const float* __restrict__ w1, const float* __restrict__ w2,
                          const float* __restrict__ hw1, const float* __restrict__ hw2,
                          __nv_bfloat16* __restrict__ hi, __nv_bfloat16* __restrict__ lo) {
    int idx = blockIdx.x * 256 + threadIdx.x;
    if (idx >= 12 * 16384) return;
    int slot = idx >> 14, off = idx & 16383;
    int k = off >> 7;
    float v = 0.f;
    if (slot == 0) { if (k < IN_DIM) v = w1_0[off]; }
    else if (slot == 1) v = w2_0[off];
    else if (slot < 6) v = w1[(slot - 2) * 16384 + off];
    else if (slot < 10) v = w2[(slot - 6) * 16384 + off];
    else if (slot == 10) v = hw1[off];
    else v = hw2[off];
    __nv_bfloat16 h = __float2bfloat16(v);
    hi[idx] = h;
    lo[idx] = __float2bfloat16(v - __bfloat162float(h));
}

// ======================= CSR build =======================
__global__ void count_deg_k(const int* __restrict__ dst, int* __restrict__ deg) {
    int e = blockIdx.x * blockDim.x + threadIdx.x;
    if (e < N_EDGES) atomicAdd(&deg[dst[e]], 1);
}

// single-block scan: rowptr (size N+1) + cursor (start offsets)
__global__ void scan_csr_k(const int* __restrict__ deg, int* __restrict__ rowptr,
                           int* __restrict__ cursor) {
    __shared__ int warpS[32];
    __shared__ int warpOff[32];
    __shared__ int carryS;
    int tid = threadIdx.x, lane = tid & 31, w = tid >> 5;
    if (tid == 0) { carryS = 0; rowptr[0] = 0; }
    __syncthreads();
    for (int base = 0; base < N_NODES; base += 1024) {
        int i = base + tid;
        int v = (i < N_NODES) ? deg[i] : 0;
        int x = v;
        #pragma unroll
        for (int o = 1; o < 32; o <<= 1) {
            int t = __shfl_up_sync(0xFFFFFFFFu, x, o);
            if (lane >= o) x += t;
        }
        if (lane == 31) warpS[w] = x;
        __syncthreads();
        if (w == 0) {
            int y = warpS[lane];
            int z = y;
            #pragma unroll
            for (int o = 1; o < 32; o <<= 1) {
                int t = __shfl_up_sync(0xFFFFFFFFu, z, o);
                if (lane >= o) z += t;
            }
            warpOff[lane] = z - y;     // exclusive
            if (lane == 31) warpS[0] = z;   // chunk total (reuse slot after read)
        }
        __syncthreads();
        int c = carryS;
        int incl = x + warpOff[w];
        if (i < N_NODES) {
            rowptr[i + 1] = c + incl;
            cursor[i] = c + incl - v;
        }
        int chunkTot = warpS[0];
        __syncthreads();
        if (tid == 0) carryS = c + chunkTot;
        __syncthreads();
    }
}

__global__ void fill_csr_k(const int* __restrict__ src, const int* __restrict__ dst,
                           const float* __restrict__ ea, int* __restrict__ cursor,
                           int* __restrict__ srcp, float4* __restrict__ eap) {
    int e = blockIdx.x * blockDim.x + threadIdx.x;
    if (e < N_EDGES) {
        int p = atomicAdd(&cursor[dst[e]], 1);
        srcp[p] = src[e];
        float4 t;
        t.x = ea[(size_t)e * 3];
        t.y = ea[(size_t)e * 3 + 1];
        t.z = ea[(size_t)e * 3 + 2];
        t.w = 0.f;
        eap[p] = t;
    }
}

// ======================= aggregation =======================
// layer0: D=11, 4 nodes per 128-thread block
__global__ void aggregate11_k(const float* __restrict__ h, const float4* __restrict__ eap,
                              const float* __restrict__ ew, const float* __restrict__ eb,
                              const float* __restrict__ epsp,
                              const int* __restrict__ srcp, const int* __restrict__ rowptr,
                              float* __restrict__ out) {
    int n = blockIdx.x * 4 + (threadIdx.x >> 5);
    int d = threadIdx.x & 31;
    if (n >= N_NODES || d >= IN_DIM) return;
    float w0 = ew[d], w1 = ew[IN_DIM + d], w2 = ew[2 * IN_DIM + d], b = eb[d];
    int s0 = rowptr[n], s1 = rowptr[n + 1];
    float acc = 0.f;
    int p = s0;
    for (; p + 2 <= s1; p += 2) {
        int i0 = srcp[p], i1 = srcp[p + 1];
        float4 e0 = eap[p], e1 = eap[p + 1];
        float gg0 = h[(size_t)i0 * IN_DIM + d];
        float gg1 = h[(size_t)i1 * IN_DIM + d];
        acc += fmaxf(gg0 + e0.x * w0 + e0.y * w1 + e0.z * w2 + b, 0.f);
        acc += fmaxf(gg1 + e1.x * w0 + e1.y * w1 + e1.z * w2 + b, 0.f);
    }
    for (; p < s1; p++) {
        int i0 = srcp[p];
        float4 e0 = eap[p];
        acc += fmaxf(h[(size_t)i0 * IN_DIM + d] + e0.x * w0 + e0.y * w1 + e0.z * w2 + b, 0.f);
    }
    float eps = *epsp;
    out[(size_t)n * IN_DIM + d] = (1.f + eps) * h[(size_t)n * IN_DIM + d] + acc;
}

// HID layers: 2 nodes per 256-thread block, unroll-4 gather pipeline
__global__ void __launch_bounds__(256)
aggregate128_k(const float* __restrict__ h, const float4* __restrict__ eap,
               const float* __restrict__ ew, const float* __restrict__ eb,
               const float* __restrict__ epsp,
               const int* __restrict__ srcp, const int* __restrict__ rowptr,
               float* __restrict__ out) {
    int n = blockIdx.x * 2 + (threadIdx.x >> 7);
    int d = threadIdx.x & 127;
    if (n >= N_NODES) return;
    float w0 = ew[d], w1 = ew[HID + d], w2 = ew[2 * HID + d], b = eb[d];
    int s0 = rowptr[n], s1 = rowptr[n + 1];
    float acc = 0.f;
    int p = s0;
    for (; p + 4 <= s1; p += 4) {
        int i0 = srcp[p], i1 = srcp[p + 1], i2 = srcp[p + 2], i3 = srcp[p + 3];
        float4 e0 = eap[p], e1 = eap[p + 1], e2 = eap[p + 2], e3 = eap[p + 3];
        float gg0 = h[(size_t)i0 * HID + d];
        float gg1 = h[(size_t)i1 * HID + d];
        float gg2 = h[(size_t)i2 * HID + d];
        float gg3 = h[(size_t)i3 * HID + d];
        acc += fmaxf(gg0 + e0.x * w0 + e0.y * w1 + e0.z * w2 + b, 0.f);
        acc += fmaxf(gg1 + e1.x * w0 + e1.y * w1 + e1.z * w2 + b, 0.f);
        acc += fmaxf(gg2 + e2.x * w0 + e2.y * w1 + e2.z * w2 + b, 0.f);
        acc += fmaxf(gg3 + e3.x * w0 + e3.y * w1 + e3.z * w2 + b, 0.f);
    }
    for (; p < s1; p++) {
        int i0 = srcp[p];
        float4 e0 = eap[p];
        acc += fmaxf(h[(size_t)i0 * HID + d] + e0.x * w0 + e0.y * w1 + e0.z * w2 + b, 0.f);
    }
    float eps = *epsp;
    out[(size_t)n * HID + d] = (1.f + eps) * h[(size_t)n * HID + d] + acc;
}

// ======================= fused 2-GEMM MLP =======================
// C[M,128] = act2( relu(A[M,Kact] @ W1 + b1) @ W2 + b2 ), with optional BN stats.
// W1/W2 are pre-split bf16 hi/lo [128][128] row-major [k][n].
// fp32 accuracy via hi/lo 3-pass mma.
#define APAD 136
#define SX_HI   0
#define SX_LO   34816
#define SY_HI   69632
#define SY_LO   104448
#define S_B1    139264
#define S_B2    139776
#define S_STAT  140288
#define SM_TOTAL (S_STAT + 2048)
#define STG_PITCH 130

__global__ void __launch_bounds__(256, 1)
gemm_mlp_k(const float* __restrict__ A, int M, int Kact, int Apitch,
           const __nv_bfloat16* __restrict__ W1hi, const __nv_bfloat16* __restrict__ W1lo,
           const float* __restrict__ b1,
           const __nv_bfloat16* __restrict__ W2hi, const __nv_bfloat16* __restrict__ W2lo,
           const float* __restrict__ b2,
           float* __restrict__ C, int do_relu2,
           float* __restrict__ ssum, float* __restrict__ ssq, int nsteps1) {
    extern __shared__ __align__(16) char smem[];
    __nv_bfloat16* aHi = (__nv_bfloat16*)(smem + SX_HI);
    __nv_bfloat16* aLo = (__nv_bfloat16*)(smem + SX_LO);
    __nv_bfloat16* wHi = (__nv_bfloat16*)(smem + SY_HI);
    __nv_bfloat16* wLo = (__nv_bfloat16*)(smem + SY_LO);
    float* b1S = (float*)(smem + S_B1);
    float* b2S = (float*)(smem + S_B2);
    float* statS = (float*)(smem + S_STAT);

    int tid = threadIdx.x;
    int lane = tid & 31;
    int wid = tid >> 5;
    int rowBase = blockIdx.x * 128;
    int kmax1 = nsteps1 << 4;

    if (tid < HID) { b1S[tid] = b1[tid]; b2S[tid] = b2[tid]; }

    // ---- load + split A [128 x kmax1] ----
    if (Kact == HID) {
        // vectorized: 32 float4 per row
        for (int idx = tid; idx < 128 * 32; idx += 256) {
            int r = idx >> 5, seg = idx & 31;
            int gr = rowBase + r;
            float4 v = (gr < M) ? __ldg((const float4*)(A + (size_t)gr * Apitch) + seg)
                                : make_float4(0.f, 0.f, 0.f, 0.f);
            __nv_bfloat16 h0 = __float2bfloat16(v.x), h1 = __float2bfloat16(v.y);
            __nv_bfloat16 h2 = __float2bfloat16(v.z), h3 = __float2bfloat16(v.w);
            __nv_bfloat16 l0 = __float2bfloat16(v.x - __bfloat162float(h0));
            __nv_bfloat16 l1 = __float2bfloat16(v.y - __bfloat162float(h1));
            __nv_bfloat16 l2 = __float2bfloat16(v.z - __bfloat162float(h2));
            __nv_bfloat16 l3 = __float2bfloat16(v.w - __bfloat162float(h3));
            __nv_bfloat162* ph = (__nv_bfloat162*)&aHi[r * APAD + seg * 4];
            __nv_bfloat162* pl = (__nv_bfloat162*)&aLo[r * APAD + seg * 4];
            ph[0] = __nv_bfloat162(h0, h1); ph[1] = __nv_bfloat162(h2, h3);
            pl[0] = __nv_bfloat162(l0, l1); pl[1] = __nv_bfloat162(l2, l3);
        }
    } else {
        for (int idx = tid; idx < 128 * 16; idx += 256) {
            int r = idx >> 4, k = idx & 15;
            int gr = rowBase + r;
            float a = (gr < M && k < Kact) ? __ldg(A + (size_t)gr * Apitch + k) : 0.f;
            __nv_bfloat16 h = __float2bfloat16(a);
            aHi[r * APAD + k] = h;
            aLo[r * APAD + k] = __float2bfloat16(a - __bfloat162float(h));
        }
    }
    // ---- load W1 (pre-split bf16): kmax1 rows x 128, 16B vector copies ----
    for (int idx = tid; idx < kmax1 * 16; idx += 256) {
        int k = idx >> 4, seg = idx & 15;
        *(uint4*)&wHi[k * APAD + seg * 8] = __ldg((const uint4*)(W1hi + k * HID) + seg);
        *(uint4*)&wLo[k * APAD + seg * 8] = __ldg((const uint4*)(W1lo + k * HID) + seg);
    }
    __syncthreads();

    // ---- warp tiling: 8 warps = 4 x 2; warp tile 32 x 64 ----
    int warpR = (wid >> 1) << 5;
    int warpC = (wid & 1) << 6;
    uint32_t aBase = smem_u32(aHi);
    uint32_t wBase = smem_u32(wHi);
    float acc[2][8][4];

    #pragma unroll
    for (int m = 0; m < 2; m++)
        #pragma unroll
        for (int j = 0; j < 8; j++)
            #pragma unroll
            for (int q = 0; q < 4; q++) acc[m][j][q] = 0.f;

    // ================= pass 1 =================
    for (int s = 0; s < nsteps1; s++) {
        int k0 = s << 4;
        uint32_t aAddr = aBase +
            ((uint32_t)((warpR + (lane & 15)) * APAD + k0 + ((lane >> 4) << 3)) << 1);
        uint32_t ah0[4], ah1[4], al0[4], al1[4];
        LDSM_X4(ah0[0], ah0[1], ah0[2], ah0[3], aAddr);
        LDSM_X4(ah1[0], ah1[1], ah1[2], ah1[3], aAddr + 16 * APAD * 2);
        LDSM_X4(al0[0], al0[1], al0[2], al0[3], aAddr + (SX_LO - SX_HI));
        LDSM_X4(al1[0], al1[1], al1[2], al1[3], aAddr + (SX_LO - SX_HI) + 16 * APAD * 2);

        uint32_t bAddr = wBase +
            ((uint32_t)((k0 + (lane & 7) + ((lane >> 3) & 1) * 8) * APAD +
                        warpC + ((lane >> 4) << 3)) << 1);
        uint32_t bh[8][2], bl[8][2];
        #pragma unroll
        for (int pp = 0; pp < 4; pp++) {
            uint32_t r0, r1, r2, r3;
            LDSM_X4T(r0, r1, r2, r3, bAddr + pp * 32);
            bh[2 * pp][0] = r0; bh[2 * pp][1] = r1;
            bh[2 * pp + 1][0] = r2; bh[2 * pp + 1][1] = r3;
            LDSM_X4T(r0, r1, r2, r3, bAddr + (SY_LO - SY_HI) + pp * 32);
            bl[2 * pp][0] = r0; bl[2 * pp][1] = r1;
            bl[2 * pp + 1][0] = r2; bl[2 * pp + 1][1] = r3;
        }
        #pragma unroll
        for (int j = 0; j < 8; j++) {
            mma_bf16(acc[0][j], ah0, bh[j]);
            mma_bf16(acc[1][j], ah1, bh[j]);
            mma_bf16(acc[0][j], ah0, bl[j]);
            mma_bf16(acc[1][j], ah1, bl[j]);
            mma_bf16(acc[0][j], al0, bh[j]);
            mma_bf16(acc[1][j], al1, bh[j]);
        }
    }
    __syncthreads();    // everyone done reading X (A) and Y (W1)

    // ---- T1 = relu(acc + b1) -> split into X region; load W2 into Y ----
    #pragma unroll
    for (int m = 0; m < 2; m++) {
        #pragma unroll
        for (int j = 0; j < 8; j++) {
            #pragma unroll
            for (int q = 0; q < 4; q++) {
                int row = warpR + m * 16 + (lane >> 2) + ((q >> 1) << 3);
                int col = warpC + j * 8 + ((lane & 3) << 1) + (q & 1);
                float t = fmaxf(acc[m][j][q] + b1S[col], 0.f);
                __nv_bfloat16 h = __float2bfloat16(t);
                aHi[row * APAD + col] = h;
                aLo[row * APAD + col] = __float2bfloat16(t - __bfloat162float(h));
            }
        }
    }
    for (int idx = tid; idx < 128 * 16; idx += 256) {
        int k = idx >> 4, seg = idx & 15;
        *(uint4*)&wHi[k * APAD + seg * 8] = __ldg((const uint4*)(W2hi + k * HID) + seg);
        *(uint4*)&wLo[k * APAD + seg * 8] = __ldg((const uint4*)(W2lo + k * HID) + seg);
    }
    __syncthreads();

    // ================= pass 2 (K = 128) =================
    #pragma unroll
    for (int m = 0; m < 2; m++)
        #pragma unroll
        for (int j = 0; j < 8; j++)
            #pragma unroll
            for (int q = 0; q < 4; q++) acc[m][j][q] = 0.f;

    for (int s = 0; s < 8; s++) {
        int k0 = s << 4;
        uint32_t aAddr = aBase +
            ((uint32_t)((warpR + (lane & 15)) * APAD + k0 + ((lane >> 4) << 3)) << 1);
        uint32_t ah0[4], ah1[4], al0[4], al1[4];
        LDSM_X4(ah0[0], ah0[1], ah0[2], ah0[3], aAddr);
        LDSM_X4(ah1[0], ah1[1], ah1[2], ah1[3], aAddr + 16 * APAD * 2);
        LDSM_X4(al0[0], al0[1], al0[2], al0[3], aAddr + (SX_LO - SX_HI));
        LDSM_X4(al1[0], al1[1], al1[2], al1[3], aAddr + (SX_LO - SX_HI) + 16 * APAD * 2);

        uint32_t bAddr = wBase +
            ((uint32_t)((k0 + (lane & 7) + ((lane >> 3) & 1) * 8) * APAD +
                        warpC + ((lane >> 4) << 3)) << 1);
        uint32_t bh[8][2], bl[8][2];
        #pragma unroll
        for (int pp = 0; pp < 4; pp++) {
            uint32_t r0, r1, r2, r3;
            LDSM_X4T(r0, r1, r2, r3, bAddr + pp * 32);
            bh[2 * pp][0] = r0; bh[2 * pp][1] = r1;
            bh[2 * pp + 1][0] = r2; bh[2 * pp + 1][1] = r3;
            LDSM_X4T(r0, r1, r2, r3, bAddr + (SY_LO - SY_HI) + pp * 32);
            bl[2 * pp][0] = r0; bl[2 * pp][1] = r1;
            bl[2 * pp + 1][0] = r2; bl[2 * pp + 1][1] = r3;
        }
        #pragma unroll
        for (int j = 0; j < 8; j++) {
            mma_bf16(acc[0][j], ah0, bh[j]);
            mma_bf16(acc[1][j], ah1, bh[j]);
            mma_bf16(acc[0][j], ah0, bl[j]);
            mma_bf16(acc[1][j], ah1, bl[j]);
            mma_bf16(acc[0][j], al0, bh[j]);
            mma_bf16(acc[1][j], al1, bh[j]);
        }
    }
    __syncthreads();    // done reading X; reuse as float staging

    // ---- epilogue: stage to smem ----
    float* stg = (float*)smem;
    #pragma unroll
    for (int m = 0; m < 2; m++) {
        #pragma unroll
        for (int j = 0; j < 8; j++) {
            int row = warpR + m * 16 + (lane >> 2);
            int col = warpC + j * 8 + ((lane & 3) << 1);
            stg[row * STG_PITCH + col]       = acc[m][j][0];
            stg[row * STG_PITCH + col + 1]   = acc[m][j][1];
            stg[(row + 8) * STG_PITCH + col]     = acc[m][j][2];
            stg[(row + 8) * STG_PITCH + col + 1] = acc[m][j][3];
        }
    }
    __syncthreads();

    // ---- coalesced store + bias2/relu2 + fused BN stats ----
    {
        int c = tid & 127, hh = tid >> 7;
        float bia = b2S[c];
        float s0 = 0.f, q0 = 0.f;
        #pragma unroll 4
        for (int j = 0; j < 64; j++) {
            int r = hh * 64 + j;
            int gr = rowBase + r;
            if (gr < M) {
                float v = stg[r * STG_PITCH + c] + bia;
                if (do_relu2) v = fmaxf(v, 0.f);
                C[(size_t)gr * HID + c] = v;
                s0 += v;
                q0 += v * v;
            }
        }
        if (ssum) {
            statS[hh * 128 + c] = s0;
            statS[256 + hh * 128 + c] = q0;
            __syncthreads();
            if (tid < 128) {
                atomicAdd(&ssum[tid], statS[tid] + statS[128 + tid]);
                atomicAdd(&ssq[tid], statS[256 + tid] + statS[384 + tid]);
            }
        }
    }
}

// ======================= BN + relu + optional residual (float4) =======================
__global__ void bn_relu_res_k(const float4* __restrict__ tmp, const float* __restrict__ stats,
                              const float* __restrict__ gamma, const float* __restrict__ beta,
                              const float4* __restrict__ res, float4* __restrict__ out,
                              int n_rows) {
    size_t i = (size_t)blockIdx.x * blockDim.x + threadIdx.x;
    size_t total = (size_t)n_rows * 32;
    if (i >= total) return;
    int d = ((int)(i & 31)) << 2;
    float invN = 1.f / (float)n_rows;
    float4 t = tmp[i];
    float4 o;
    {
        float mu = stats[d] * invN;
        float var = stats[HID + d] * invN - mu * mu;
        o.x = fmaxf((t.x - mu) * rsqrtf(var + BN_EPS) * gamma[d] + beta[d], 0.f);
    }
    {
        float mu = stats[d + 1] * invN;
        float var = stats[HID + d + 1] * invN - mu * mu;
        o.y = fmaxf((t.y - mu) * rsqrtf(var + BN_EPS) * gamma[d + 1] + beta[d + 1], 0.f);
    }
    {
        float mu = stats[d + 2] * invN;
        float var = stats[HID + d + 2] * invN - mu * mu;
        o.z = fmaxf((t.z - mu) * rsqrtf(var + BN_EPS) * gamma[d + 2] + beta[d + 2], 0.f);
    }
    {
        float mu = stats[d + 3] * invN;
        float var = stats[HID + d + 3] * invN - mu * mu;
        o.w = fmaxf((t.w - mu) * rsqrtf(var + BN_EPS) * gamma[d + 3] + beta[d + 3], 0.f);
    }
    if (res) {
        float4 r = res[i];
        o.x += r.x; o.y += r.y; o.z += r.z; o.w += r.w;
    }
    out[i] = o;
}

// ======================= pooling =======================
__global__ void graph_ptr_k(const int* __restrict__ batch, int* __restrict__ gptr) {
    int g = blockIdx.x * blockDim.x + threadIdx.x;
    if (g > N_GRAPHS) return;
    int lo = 0, hi = N_NODES;
    while (lo < hi) {
        int mid = (lo + hi) >> 1;
        if (batch[mid] < g) lo = mid + 1; else hi = mid;
    }
    gptr[g] = lo;
}
__global__ void pool_k(const float* __restrict__ h, const int* __restrict__ gptr,
                       float* __restrict__ pooled) {
    int g = blockIdx.x;
    int d = threadIdx.x;
    int a = gptr[g], b = gptr[g + 1];
    float acc = 0.f;
    for (int n = a; n < b; n++) acc += h[(size_t)n * HID + d];
    int cnt = b - a;
    float c = (float)(cnt > 1 ? cnt : 1);
    pooled[(size_t)g * HID + d] = acc / c;
}

// ======================= head final dot =======================
__global__ void head_out_k(const float* __restrict__ z, const float* __restrict__ w,
                           const float* __restrict__ b, float* __restrict__ out) {
    int g = blockIdx.x;
    int t = threadIdx.x; // 128
    float v = z[(size_t)g * HID + t] * w[t];
    #pragma unroll
    for (int off = 16; off; off >>= 1) v += __shfl_down_sync(0xFFFFFFFFu, v, off);
    __shared__ float s[4];
    if ((t & 31) == 0) s[t >> 5] = v;
    __syncthreads();
    if (t == 0) out[g] = s[0] + s[1] + s[2] + s[3] + b[0];
}

// ======================= host =======================
static void* sym_addr(const void* sym) {
    void* p = nullptr;
    cudaGetSymbolAddress(&p, sym);
    return p;
}

extern "C" void kernel_launch(void* const* d_in, const int* in_sizes, int n_in,
                              void* d_out, int out_size) {
    const float* x        = (const float*)d_in[0];
    const float* edge_attr= (const float*)d_in[1];
    const float* e_w0     = (const float*)d_in[2];
    const float* e_b0     = (const float*)d_in[3];
    const float* w1_0     = (const float*)d_in[4];
    const float* b1_0     = (const float*)d_in[5];
    const float* w2_0     = (const float*)d_in[6];
    const float* b2_0     = (const float*)d_in[7];
    const float* gamma0   = (const float*)d_in[8];
    const float* beta0    = (const float*)d_in[9];
    const float* eps0     = (const float*)d_in[10];
    const float* e_w      = (const float*)d_in[11];
    const float* e_b      = (const float*)d_in[12];
    const float* w1       = (const float*)d_in[13];
    const float* b1       = (const float*)d_in[14];
    const float* w2       = (const float*)d_in[15];
    const float* b2       = (const float*)d_in[16];
    const float* gamma    = (const float*)d_in[17];
    const float* beta     = (const float*)d_in[18];
    const float* eps_r    = (const float*)d_in[19];
    const float* hw1      = (const float*)d_in[20];
    const float* hb1      = (const float*)d_in[21];
    const float* hw2      = (const float*)d_in[22];
    const float* hb2      = (const float*)d_in[23];
    const float* hw3      = (const float*)d_in[24];
    const float* hb3      = (const float*)d_in[25];
    const int*   edge_index = (const int*)d_in[26];
    const int*   batch    = (const int*)d_in[27];

    const int* src = edge_index;
    const int* dst = edge_index + N_EDGES;

    float* pre   = (float*)sym_addr(g_pre);
    float* tmp   = (float*)sym_addr(g_tmp);
    float* hA    = (float*)sym_addr(g_hA);
    float* hB    = (float*)sym_addr(g_hB);
    int*   deg   = (int*)sym_addr(g_deg);
    int*   rowptr= (int*)sym_addr(g_rowptr);
    int*   cursor= (int*)sym_addr(g_cursor);
    int*   srcp  = (int*)sym_addr(g_srcp);
    float4* eap  = (float4*)sym_addr(g_eap);
    int*   gptr  = (int*)sym_addr(g_gptr);
    float* stats = (float*)sym_addr(g_stats);
    float* pool  = (float*)sym_addr(g_pool);
    float* z2    = (float*)sym_addr(g_z2);
    __nv_bfloat16* whi = (__nv_bfloat16*)sym_addr(g_whi);
    __nv_bfloat16* wlo = (__nv_bfloat16*)sym_addr(g_wlo);
    float* out   = (float*)d_out;

    cudaFuncSetAttribute(gemm_mlp_k, cudaFuncAttributeMaxDynamicSharedMemorySize, SM_TOTAL);

    const int SLOT = 128 * 128;

    // ---- CSR build + weight split ----
    cudaMemsetAsync(deg, 0, N_NODES * sizeof(int), 0);
    split_w_k<<<(12 * 16384 + 255) / 256, 256>>>(w1_0, w2_0, w1, w2, hw1, hw2, whi, wlo);
    count_deg_k<<<(N_EDGES + 255) / 256, 256>>>(dst, deg);
    scan_csr_k<<<1, 1024>>>(deg, rowptr, cursor);
    fill_csr_k<<<(N_EDGES + 255) / 256, 256>>>(src, dst, edge_attr, cursor, srcp, eap);

    const int GB_N = (N_NODES + 127) / 128;
    const int GB_G = (N_GRAPHS + 127) / 128;
    const int BN_BLOCKS = (int)(((size_t)N_NODES * 32 + 255) / 256);

    // ---- layer 0 ----
    aggregate11_k<<<(N_NODES + 3) / 4, 128>>>(x, eap, e_w0, e_b0, eps0, srcp, rowptr, pre);
    cudaMemsetAsync(stats, 0, 2 * HID * sizeof(float), 0);
    gemm_mlp_k<<<GB_N, 256, SM_TOTAL>>>(pre, N_NODES, IN_DIM, IN_DIM,
                                        whi + 0 * SLOT, wlo + 0 * SLOT, b1_0,
                                        whi + 1 * SLOT, wlo + 1 * SLOT, b2_0,
                                        tmp, 0, stats, stats + HID, 1);
    bn_relu_res_k<<<BN_BLOCKS, 256>>>((const float4*)tmp, stats, gamma0, beta0,
                                      nullptr, (float4*)hA, N_NODES);

    // ---- layers 1..4 ----
    float* cur = hA;
    float* nxt = hB;
    for (int i = 0; i < N_REST; i++) {
        aggregate128_k<<<(N_NODES + 1) / 2, 256>>>(cur, eap, e_w + (size_t)i * 3 * HID,
                                                   e_b + (size_t)i * HID, eps_r + i,
                                                   srcp, rowptr, pre);
        cudaMemsetAsync(stats, 0, 2 * HID * sizeof(float), 0);
        gemm_mlp_k<<<GB_N, 256, SM_TOTAL>>>(pre, N_NODES, HID, HID,
                                            whi + (2 + i) * SLOT, wlo + (2 + i) * SLOT,
                                            b1 + (size_t)i * HID,
                                            whi + (6 + i) * SLOT, wlo + (6 + i) * SLOT,
                                            b2 + (size_t)i * HID,
                                            tmp, 0, stats, stats + HID, 8);
        bn_relu_res_k<<<BN_BLOCKS, 256>>>((const float4*)tmp, stats,
                                          gamma + (size_t)i * HID, beta + (size_t)i * HID,
                                          (const float4*)cur, (float4*)nxt, N_NODES);
        float* t = cur; cur = nxt; nxt = t;
    }

    // ---- pooling ----
    graph_ptr_k<<<(N_GRAPHS + 1 + 127) / 128, 128>>>(batch, gptr);
    pool_k<<<N_GRAPHS, HID>>>(cur, gptr, pool);

    // ---- head: z2 = relu(relu(pool@hw1+hb1)@hw2+hb2) fused ----
    gemm_mlp_k<<<GB_G, 256, SM_TOTAL>>>(pool, N_GRAPHS, HID, HID,
                                        whi + 10 * SLOT, wlo + 10 * SLOT, hb1,
                                        whi + 11 * SLOT, wlo + 11 * SLOT, hb2,
                                        z2, 1, nullptr, nullptr, 8);
    head_out_k<<<N_GRAPHS, HID>>>(z2, hw3, hb3, out);
}

// round 5
// speedup vs baseline: 1.9664x; 1.3934x over previous
#include <cuda_runtime.h>
#include <cuda_bf16.h>
#include <cstdint>

#define N_NODES 100000
#define N_EDGES 600000
#define N_GRAPHS 5000
#define IN_DIM 11
#define HID 128
#define EDGE_DIM 3
#define N_REST 4
#define BN_EPS 1e-5f

// ======================= PTX helpers (baseline sm_80+ ISA only) =======================
__device__ __forceinline__ uint32_t smem_u32(const void* p) {
    uint32_t a;
    asm("{ .reg .u64 t; cvta.to.shared.u64 t, %1; cvt.u32.u64 %0, t; }" : "=r"(a) : "l"(p));
    return a;
}

#define LDSM_X4(r0, r1, r2, r3, addr)                                            \
    asm volatile("ldmatrix.sync.aligned.m8n8.x4.shared.b16 {%0,%1,%2,%3}, [%4];" \
                 : "=r"(r0), "=r"(r1), "=r"(r2), "=r"(r3) : "r"(addr))

#define LDSM_X4T(r0, r1, r2, r3, addr)                                                 \
    asm volatile("ldmatrix.sync.aligned.m8n8.x4.trans.shared.b16 {%0,%1,%2,%3}, [%4];" \
                 : "=r"(r0), "=r"(r1), "=r"(r2), "=r"(r3) : "r"(addr))

__device__ __forceinline__ void mma_bf16(float* c, const uint32_t* a, const uint32_t* b) {
    asm volatile(
        "mma.sync.aligned.m16n8k16.row.col.f32.bf16.bf16.f32 "
        "{%0,%1,%2,%3}, {%4,%5,%6,%7}, {%8,%9}, {%0,%1,%2,%3};"
        : "+f"(c[0]), "+f"(c[1]), "+f"(c[2]), "+f"(c[3])
        : "r"(a[0]), "r"(a[1]), "r"(a[2]), "r"(a[3]), "r"(b[0]), "r"(b[1]));
}

// ======================= scratch =======================
__device__ float g_pre[(size_t)N_NODES * HID];
__device__ float g_tmp[(size_t)N_NODES * HID];
__device__ float g_hA[(size_t)N_NODES * HID];
__device__ float g_hB[(size_t)N_NODES * HID];

__device__ int g_deg[N_NODES];
__device__ int g_rowptr[N_NODES + 1];
__device__ int g_cursor[N_NODES + 1];
__device__ int g_srcp[N_EDGES];
__device__ float4 g_eap[N_EDGES];
__device__ int g_gptr[N_GRAPHS + 1];

__device__ float g_stats[5 * 2 * HID];          // per-layer (sum, sumsq)
__device__ float g_pool[(size_t)N_GRAPHS * HID];
__device__ float g_z2[(size_t)N_GRAPHS * HID];

// pre-split weights: 12 slots of [128][128] bf16 (slot0 = w1_0 zero-padded past row 10)
__device__ __nv_bfloat16 g_whi[12 * 128 * 128];
__device__ __nv_bfloat16 g_wlo[12 * 128 * 128];

// ======================= init: zero deg + stats, split weights =======================
__global__ void init_k(const float* __restrict__ w1_0, const float* __restrict__ w2_0,
                       const float* __restrict__ w1, const float* __restrict__ w2,
                       const float* __restrict__ hw1, const float* __restrict__ hw2,
                       __nv_bfloat16* __restrict__ hi, __nv_bfloat16* __restrict__ lo,
                       int* __restrict__ deg, float* __restrict__ stats) {
    int idx = blockIdx.x * 256 + threadIdx.x;
    if (idx < N_NODES) deg[idx] = 0;
    if (idx < 5 * 2 * HID) stats[idx] = 0.f;
    if (idx >= 12 * 16384) return;
    int slot = idx >> 14, off = idx & 16383;
    int k = off >> 7;
    float v = 0.f;
    if (slot == 0) { if (k < IN_DIM) v = w1_0[off]; }
    else if (slot == 1) v = w2_0[off];
    else if (slot < 6) v = w1[(slot - 2) * 16384 + off];
    else if (slot < 10) v = w2[(slot - 6) * 16384 + off];
    else if (slot == 10) v = hw1[off];
    else v = hw2[off];
    __nv_bfloat16 h = __float2bfloat16(v);
    hi[idx] = h;
    lo[idx] = __float2bfloat16(v - __bfloat162float(h));
}

// ======================= CSR build =======================
__global__ void count_deg_k(const int* __restrict__ dst, int* __restrict__ deg) {
    int e = blockIdx.x * blockDim.x + threadIdx.x;
    if (e < N_EDGES) atomicAdd(&deg[dst[e]], 1);
}

__global__ void scan_csr_k(const int* __restrict__ deg, int* __restrict__ rowptr,
                           int* __restrict__ cursor) {
    __shared__ int warpS[32];
    __shared__ int warpOff[32];
    __shared__ int carryS;
    int tid = threadIdx.x, lane = tid & 31, w = tid >> 5;
    if (tid == 0) { carryS = 0; rowptr[0] = 0; }
    __syncthreads();
    for (int base = 0; base < N_NODES; base += 1024) {
        int i = base + tid;
        int v = (i < N_NODES) ? deg[i] : 0;
        int x = v;
        #pragma unroll
        for (int o = 1; o < 32; o <<= 1) {
            int t = __shfl_up_sync(0xFFFFFFFFu, x, o);
            if (lane >= o) x += t;
        }
        if (lane == 31) warpS[w] = x;
        __syncthreads();
        if (w == 0) {
            int y = warpS[lane];
            int z = y;
            #pragma unroll
            for (int o = 1; o < 32; o <<= 1) {
                int t = __shfl_up_sync(0xFFFFFFFFu, z, o);
                if (lane >= o) z += t;
            }
            warpOff[lane] = z - y;
            if (lane == 31) warpS[0] = z;
        }
        __syncthreads();
        int c = carryS;
        int incl = x + warpOff[w];
        if (i < N_NODES) {
            rowptr[i + 1] = c + incl;
            cursor[i] = c + incl - v;
        }
        int chunkTot = warpS[0];
        __syncthreads();
        if (tid == 0) carryS = c + chunkTot;
        __syncthreads();
    }
}

__global__ void fill_csr_k(const int* __restrict__ src, const int* __restrict__ dst,
                           const float* __restrict__ ea, int* __restrict__ cursor,
                           int* __restrict__ srcp, float4* __restrict__ eap) {
    int e = blockIdx.x * blockDim.x + threadIdx.x;
    if (e < N_EDGES) {
        int p = atomicAdd(&cursor[dst[e]], 1);
        srcp[p] = src[e];
        float4 t;
        t.x = ea[(size_t)e * 3];
        t.y = ea[(size_t)e * 3 + 1];
        t.z = ea[(size_t)e * 3 + 2];
        t.w = 0.f;
        eap[p] = t;
    }
}

// ======================= aggregation =======================
__global__ void aggregate11_k(const float* __restrict__ h, const float4* __restrict__ eap,
                              const float* __restrict__ ew, const float* __restrict__ eb,
                              const float* __restrict__ epsp,
                              const int* __restrict__ srcp, const int* __restrict__ rowptr,
                              float* __restrict__ out) {
    int n = blockIdx.x * 4 + (threadIdx.x >> 5);
    int d = threadIdx.x & 31;
    if (n >= N_NODES || d >= IN_DIM) return;
    float w0 = ew[d], w1 = ew[IN_DIM + d], w2 = ew[2 * IN_DIM + d], b = eb[d];
    int s0 = rowptr[n], s1 = rowptr[n + 1];
    float acc = 0.f;
    int p = s0;
    for (; p + 2 <= s1; p += 2) {
        int i0 = srcp[p], i1 = srcp[p + 1];
        float4 e0 = eap[p], e1 = eap[p + 1];
        float gg0 = h[(size_t)i0 * IN_DIM + d];
        float gg1 = h[(size_t)i1 * IN_DIM + d];
        acc += fmaxf(gg0 + e0.x * w0 + e0.y * w1 + e0.z * w2 + b, 0.f);
        acc += fmaxf(gg1 + e1.x * w0 + e1.y * w1 + e1.z * w2 + b, 0.f);
    }
    for (; p < s1; p++) {
        int i0 = srcp[p];
        float4 e0 = eap[p];
        acc += fmaxf(h[(size_t)i0 * IN_DIM + d] + e0.x * w0 + e0.y * w1 + e0.z * w2 + b, 0.f);
    }
    float eps = *epsp;
    out[(size_t)n * IN_DIM + d] = (1.f + eps) * h[(size_t)n * IN_DIM + d] + acc;
}

__global__ void __launch_bounds__(256)
aggregate128_k(const float* __restrict__ h, const float4* __restrict__ eap,
               const float* __restrict__ ew, const float* __restrict__ eb,
               const float* __restrict__ epsp,
               const int* __restrict__ srcp, const int* __restrict__ rowptr,
               float* __restrict__ out) {
    int n = blockIdx.x * 2 + (threadIdx.x >> 7);
    int d = threadIdx.x & 127;
    if (n >= N_NODES) return;
    float w0 = ew[d], w1 = ew[HID + d], w2 = ew[2 * HID + d], b = eb[d];
    int s0 = rowptr[n], s1 = rowptr[n + 1];
    float acc = 0.f;
    int p = s0;
    for (; p + 4 <= s1; p += 4) {
        int i0 = srcp[p], i1 = srcp[p + 1], i2 = srcp[p + 2], i3 = srcp[p + 3];
        float4 e0 = eap[p], e1 = eap[p + 1], e2 = eap[p + 2], e3 = eap[p + 3];
        float gg0 = h[(size_t)i0 * HID + d];
        float gg1 = h[(size_t)i1 * HID + d];
        float gg2 = h[(size_t)i2 * HID + d];
        float gg3 = h[(size_t)i3 * HID + d];
        acc += fmaxf(gg0 + e0.x * w0 + e0.y * w1 + e0.z * w2 + b, 0.f);
        acc += fmaxf(gg1 + e1.x * w0 + e1.y * w1 + e1.z * w2 + b, 0.f);
        acc += fmaxf(gg2 + e2.x * w0 + e2.y * w1 + e2.z * w2 + b, 0.f);
        acc += fmaxf(gg3 + e3.x * w0 + e3.y * w1 + e3.z * w2 + b, 0.f);
    }
    for (; p < s1; p++) {
        int i0 = srcp[p];
        float4 e0 = eap[p];
        acc += fmaxf(h[(size_t)i0 * HID + d] + e0.x * w0 + e0.y * w1 + e0.z * w2 + b, 0.f);
    }
    float eps = *epsp;
    out[(size_t)n * HID + d] = (1.f + eps) * h[(size_t)n * HID + d] + acc;
}

// ======================= fused 2-GEMM MLP (M=64 tiles, 2 CTAs/SM) =======================
// C[M,128] = act2( relu(A[M,Kact] @ W1 + b1) @ W2 + b2 ), optional BN stats.
// fp32 accuracy via bf16 hi/lo 3-pass mma.
#define APAD 136
#define SX_HI   0
#define SX_LO   17408
#define SY_HI   34816
#define SY_LO   69632
#define S_B1    104448
#define S_B2    104960
#define S_STAT  105472
#define SM_TOTAL (S_STAT + 2048)
#define STG_PITCH 130

__global__ void __launch_bounds__(256, 2)
gemm_mlp_k(const float* __restrict__ A, int M, int Kact, int Apitch,
           const __nv_bfloat16* __restrict__ W1hi, const __nv_bfloat16* __restrict__ W1lo,
           const float* __restrict__ b1,
           const __nv_bfloat16* __restrict__ W2hi, const __nv_bfloat16* __restrict__ W2lo,
           const float* __restrict__ b2,
           float* __restrict__ C, int do_relu2,
           float* __restrict__ ssum, float* __restrict__ ssq, int nsteps1) {
    extern __shared__ __align__(16) char smem[];
    __nv_bfloat16* aHi = (__nv_bfloat16*)(smem + SX_HI);
    __nv_bfloat16* aLo = (__nv_bfloat16*)(smem + SX_LO);
    __nv_bfloat16* wHi = (__nv_bfloat16*)(smem + SY_HI);
    __nv_bfloat16* wLo = (__nv_bfloat16*)(smem + SY_LO);
    float* b1S = (float*)(smem + S_B1);
    float* b2S = (float*)(smem + S_B2);
    float* statS = (float*)(smem + S_STAT);

    int tid = threadIdx.x;
    int lane = tid & 31;
    int wid = tid >> 5;
    int rowBase = blockIdx.x * 64;
    int kmax1 = nsteps1 << 4;

    if (tid < HID) { b1S[tid] = b1[tid]; b2S[tid] = b2[tid]; }

    // ---- load + split A [64 x kmax1] ----
    if (Kact == HID) {
        for (int idx = tid; idx < 64 * 32; idx += 256) {
            int r = idx >> 5, seg = idx & 31;
            int gr = rowBase + r;
            float4 v = (gr < M) ? __ldg((const float4*)(A + (size_t)gr * Apitch) + seg)
                                : make_float4(0.f, 0.f, 0.f, 0.f);
            __nv_bfloat16 h0 = __float2bfloat16(v.x), h1 = __float2bfloat16(v.y);
            __nv_bfloat16 h2 = __float2bfloat16(v.z), h3 = __float2bfloat16(v.w);
            __nv_bfloat16 l0 = __float2bfloat16(v.x - __bfloat162float(h0));
            __nv_bfloat16 l1 = __float2bfloat16(v.y - __bfloat162float(h1));
            __nv_bfloat16 l2 = __float2bfloat16(v.z - __bfloat162float(h2));
            __nv_bfloat16 l3 = __float2bfloat16(v.w - __bfloat162float(h3));
            __nv_bfloat162* ph = (__nv_bfloat162*)&aHi[r * APAD + seg * 4];
            __nv_bfloat162* pl = (__nv_bfloat162*)&aLo[r * APAD + seg * 4];
            ph[0] = __nv_bfloat162(h0, h1); ph[1] = __nv_bfloat162(h2, h3);
            pl[0] = __nv_bfloat162(l0, l1); pl[1] = __nv_bfloat162(l2, l3);
        }
    } else {
        for (int idx = tid; idx < 64 * 16; idx += 256) {
            int r = idx >> 4, k = idx & 15;
            int gr = rowBase + r;
            float a = (gr < M && k < Kact) ? __ldg(A + (size_t)gr * Apitch + k) : 0.f;
            __nv_bfloat16 h = __float2bfloat16(a);
            aHi[r * APAD + k] = h;
            aLo[r * APAD + k] = __float2bfloat16(a - __bfloat162float(h));
        }
    }
    // ---- load W1 (pre-split bf16): kmax1 rows x 128 ----
    for (int idx = tid; idx < kmax1 * 16; idx += 256) {
        int k = idx >> 4, seg = idx & 15;
        *(uint4*)&wHi[k * APAD + seg * 8] = __ldg((const uint4*)(W1hi + k * HID) + seg);
        *(uint4*)&wLo[k * APAD + seg * 8] = __ldg((const uint4*)(W1lo + k * HID) + seg);
    }
    __syncthreads();

    // ---- warp tiling: 8 warps = 2 (rows) x 4 (cols); warp tile 32 x 32 ----
    int warpR = (wid >> 2) << 5;
    int warpC = (wid & 3) << 5;
    uint32_t aBase = smem_u32(aHi);
    uint32_t wBase = smem_u32(wHi);
    float acc[2][4][4];

    #pragma unroll
    for (int m = 0; m < 2; m++)
        #pragma unroll
        for (int j = 0; j < 4; j++)
            #pragma unroll
            for (int q = 0; q < 4; q++) acc[m][j][q] = 0.f;

    // ================= pass 1 =================
    for (int s = 0; s < nsteps1; s++) {
        int k0 = s << 4;
        uint32_t aAddr = aBase +
            ((uint32_t)((warpR + (lane & 15)) * APAD + k0 + ((lane >> 4) << 3)) << 1);
        uint32_t ah0[4], ah1[4], al0[4], al1[4];
        LDSM_X4(ah0[0], ah0[1], ah0[2], ah0[3], aAddr);
        LDSM_X4(ah1[0], ah1[1], ah1[2], ah1[3], aAddr + 16 * APAD * 2);
        LDSM_X4(al0[0], al0[1], al0[2], al0[3], aAddr + (SX_LO - SX_HI));
        LDSM_X4(al1[0], al1[1], al1[2], al1[3], aAddr + (SX_LO - SX_HI) + 16 * APAD * 2);

        uint32_t bAddr = wBase +
            ((uint32_t)((k0 + (lane & 7) + ((lane >> 3) & 1) * 8) * APAD +
                        warpC + ((lane >> 4) << 3)) << 1);
        uint32_t bh[4][2], bl[4][2];
        #pragma unroll
        for (int pp = 0; pp < 2; pp++) {
            uint32_t r0, r1, r2, r3;
            LDSM_X4T(r0, r1, r2, r3, bAddr + pp * 32);
            bh[2 * pp][0] = r0; bh[2 * pp][1] = r1;
            bh[2 * pp + 1][0] = r2; bh[2 * pp + 1][1] = r3;
            LDSM_X4T(r0, r1, r2, r3, bAddr + (SY_LO - SY_HI) + pp * 32);
            bl[2 * pp][0] = r0; bl[2 * pp][1] = r1;
            bl[2 * pp + 1][0] = r2; bl[2 * pp + 1][1] = r3;
        }
        #pragma unroll
        for (int j = 0; j < 4; j++) {
            mma_bf16(acc[0][j], ah0, bh[j]);
            mma_bf16(acc[1][j], ah1, bh[j]);
            mma_bf16(acc[0][j], ah0, bl[j]);
            mma_bf16(acc[1][j], ah1, bl[j]);
            mma_bf16(acc[0][j], al0, bh[j]);
            mma_bf16(acc[1][j], al1, bh[j]);
        }
    }
    __syncthreads();

    // ---- T1 = relu(acc + b1) -> split into X region; load W2 into Y ----
    #pragma unroll
    for (int m = 0; m < 2; m++) {
        #pragma unroll
        for (int j = 0; j < 4; j++) {
            #pragma unroll
            for (int q = 0; q < 4; q++) {
                int row = warpR + m * 16 + (lane >> 2) + ((q >> 1) << 3);
                int col = warpC + j * 8 + ((lane & 3) << 1) + (q & 1);
                float t = fmaxf(acc[m][j][q] + b1S[col], 0.f);
                __nv_bfloat16 h = __float2bfloat16(t);
                aHi[row * APAD + col] = h;
                aLo[row * APAD + col] = __float2bfloat16(t - __bfloat162float(h));
            }
        }
    }
    for (int idx = tid; idx < 128 * 16; idx += 256) {
        int k = idx >> 4, seg = idx & 15;
        *(uint4*)&wHi[k * APAD + seg * 8] = __ldg((const uint4*)(W2hi + k * HID) + seg);
        *(uint4*)&wLo[k * APAD + seg * 8] = __ldg((const uint4*)(W2lo + k * HID) + seg);
    }
    __syncthreads();

    // ================= pass 2 (K = 128) =================
    #pragma unroll
    for (int m = 0; m < 2; m++)
        #pragma unroll
        for (int j = 0; j < 4; j++)
            #pragma unroll
            for (int q = 0; q < 4; q++) acc[m][j][q] = 0.f;

    for (int s = 0; s < 8; s++) {
        int k0 = s << 4;
        uint32_t aAddr = aBase +
            ((uint32_t)((warpR + (lane & 15)) * APAD + k0 + ((lane >> 4) << 3)) << 1);
        uint32_t ah0[4], ah1[4], al0[4], al1[4];
        LDSM_X4(ah0[0], ah0[1], ah0[2], ah0[3], aAddr);
        LDSM_X4(ah1[0], ah1[1], ah1[2], ah1[3], aAddr + 16 * APAD * 2);
        LDSM_X4(al0[0], al0[1], al0[2], al0[3], aAddr + (SX_LO - SX_HI));
        LDSM_X4(al1[0], al1[1], al1[2], al1[3], aAddr + (SX_LO - SX_HI) + 16 * APAD * 2);

        uint32_t bAddr = wBase +
            ((uint32_t)((k0 + (lane & 7) + ((lane >> 3) & 1) * 8) * APAD +
                        warpC + ((lane >> 4) << 3)) << 1);
        uint32_t bh[4][2], bl[4][2];
        #pragma unroll
        for (int pp = 0; pp < 2; pp++) {
            uint32_t r0, r1, r2, r3;
            LDSM_X4T(r0, r1, r2, r3, bAddr + pp * 32);
            bh[2 * pp][0] = r0; bh[2 * pp][1] = r1;
            bh[2 * pp + 1][0] = r2; bh[2 * pp + 1][1] = r3;
            LDSM_X4T(r0, r1, r2, r3, bAddr + (SY_LO - SY_HI) + pp * 32);
            bl[2 * pp][0] = r0; bl[2 * pp][1] = r1;
            bl[2 * pp + 1][0] = r2; bl[2 * pp + 1][1] = r3;
        }
        #pragma unroll
        for (int j = 0; j < 4; j++) {
            mma_bf16(acc[0][j], ah0, bh[j]);
            mma_bf16(acc[1][j], ah1, bh[j]);
            mma_bf16(acc[0][j], ah0, bl[j]);
            mma_bf16(acc[1][j], ah1, bl[j]);
            mma_bf16(acc[0][j], al0, bh[j]);
            mma_bf16(acc[1][j], al1, bh[j]);
        }
    }
    __syncthreads();

    // ---- epilogue: stage to smem (reuse X region) ----
    float* stg = (float*)smem;
    #pragma unroll
    for (int m = 0; m < 2; m++) {
        #pragma unroll
        for (int j = 0; j < 4; j++) {
            int row = warpR + m * 16 + (lane >> 2);
            int col = warpC + j * 8 + ((lane & 3) << 1);
            stg[row * STG_PITCH + col]       = acc[m][j][0];
            stg[row * STG_PITCH + col + 1]   = acc[m][j][1];
            stg[(row + 8) * STG_PITCH + col]     = acc[m][j][2];
            stg[(row + 8) * STG_PITCH + col + 1] = acc[m][j][3];
        }
    }
    __syncthreads();

    // ---- coalesced store + bias2/relu2 + fused BN stats ----
    {
        int c = tid & 127, hh = tid >> 7;
        float bia = b2S[c];
        float s0 = 0.f, q0 = 0.f;
        #pragma unroll 4
        for (int j = 0; j < 32; j++) {
            int r = hh * 32 + j;
            int gr = rowBase + r;
            if (gr < M) {
                float v = stg[r * STG_PITCH + c] + bia;
                if (do_relu2) v = fmaxf(v, 0.f);
                C[(size_t)gr * HID + c] = v;
                s0 += v;
                q0 += v * v;
            }
        }
        if (ssum) {
            statS[hh * 128 + c] = s0;
            statS[256 + hh * 128 + c] = q0;
            __syncthreads();
            if (tid < 128) {
                atomicAdd(&ssum[tid], statS[tid] + statS[128 + tid]);
                atomicAdd(&ssq[tid], statS[256 + tid] + statS[384 + tid]);
            }
        }
    }
}

// ======================= BN + relu + optional residual (float4) =======================
__global__ void bn_relu_res_k(const float4* __restrict__ tmp, const float* __restrict__ stats,
                              const float* __restrict__ gamma, const float* __restrict__ beta,
                              const float4* __restrict__ res, float4* __restrict__ out,
                              int n_rows) {
    size_t i = (size_t)blockIdx.x * blockDim.x + threadIdx.x;
    size_t total = (size_t)n_rows * 32;
    if (i >= total) return;
    int d = ((int)(i & 31)) << 2;
    float invN = 1.f / (float)n_rows;
    float4 t = tmp[i];
    float4 o;
    {
        float mu = stats[d] * invN;
        float var = stats[HID + d] * invN - mu * mu;
        o.x = fmaxf((t.x - mu) * rsqrtf(var + BN_EPS) * gamma[d] + beta[d], 0.f);
    }
    {
        float mu = stats[d + 1] * invN;
        float var = stats[HID + d + 1] * invN - mu * mu;
        o.y = fmaxf((t.y - mu) * rsqrtf(var + BN_EPS) * gamma[d + 1] + beta[d + 1], 0.f);
    }
    {
        float mu = stats[d + 2] * invN;
        float var = stats[HID + d + 2] * invN - mu * mu;
        o.z = fmaxf((t.z - mu) * rsqrtf(var + BN_EPS) * gamma[d + 2] + beta[d + 2], 0.f);
    }
    {
        float mu = stats[d + 3] * invN;
        float var = stats[HID + d + 3] * invN - mu * mu;
        o.w = fmaxf((t.w - mu) * rsqrtf(var + BN_EPS) * gamma[d + 3] + beta[d + 3], 0.f);
    }
    if (res) {
        float4 r = res[i];
        o.x += r.x; o.y += r.y; o.z += r.z; o.w += r.w;
    }
    out[i] = o;
}

// ======================= pooling =======================
__global__ void graph_ptr_k(const int* __restrict__ batch, int* __restrict__ gptr) {
    int g = blockIdx.x * blockDim.x + threadIdx.x;
    if (g > N_GRAPHS) return;
    int lo = 0, hi = N_NODES;
    while (lo < hi) {
        int mid = (lo + hi) >> 1;
        if (batch[mid] < g) lo = mid + 1; else hi = mid;
    }
    gptr[g] = lo;
}
__global__ void pool_k(const float* __restrict__ h, const int* __restrict__ gptr,
                       float* __restrict__ pooled) {
    int g = blockIdx.x;
    int d = threadIdx.x;
    int a = gptr[g], b = gptr[g + 1];
    float acc = 0.f;
    for (int n = a; n < b; n++) acc += h[(size_t)n * HID + d];
    int cnt = b - a;
    float c = (float)(cnt > 1 ? cnt : 1);
    pooled[(size_t)g * HID + d] = acc / c;
}

// ======================= head final dot =======================
__global__ void head_out_k(const float* __restrict__ z, const float* __restrict__ w,
                           const float* __restrict__ b, float* __restrict__ out) {
    int g = blockIdx.x;
    int t = threadIdx.x; // 128
    float v = z[(size_t)g * HID + t] * w[t];
    #pragma unroll
    for (int off = 16; off; off >>= 1) v += __shfl_down_sync(0xFFFFFFFFu, v, off);
    __shared__ float s[4];
    if ((t & 31) == 0) s[t >> 5] = v;
    __syncthreads();
    if (t == 0) out[g] = s[0] + s[1] + s[2] + s[3] + b[0];
}

// ======================= host =======================
static void* sym_addr(const void* sym) {
    void* p = nullptr;
    cudaGetSymbolAddress(&p, sym);
    return p;
}

extern "C" void kernel_launch(void* const* d_in, const int* in_sizes, int n_in,
                              void* d_out, int out_size) {
    const float* x        = (const float*)d_in[0];
    const float* edge_attr= (const float*)d_in[1];
    const float* e_w0     = (const float*)d_in[2];
    const float* e_b0     = (const float*)d_in[3];
    const float* w1_0     = (const float*)d_in[4];
    const float* b1_0     = (const float*)d_in[5];
    const float* w2_0     = (const float*)d_in[6];
    const float* b2_0     = (const float*)d_in[7];
    const float* gamma0   = (const float*)d_in[8];
    const float* beta0    = (const float*)d_in[9];
    const float* eps0     = (const float*)d_in[10];
    const float* e_w      = (const float*)d_in[11];
    const float* e_b      = (const float*)d_in[12];
    const float* w1       = (const float*)d_in[13];
    const float* b1       = (const float*)d_in[14];
    const float* w2       = (const float*)d_in[15];
    const float* b2       = (const float*)d_in[16];
    const float* gamma    = (const float*)d_in[17];
    const float* beta     = (const float*)d_in[18];
    const float* eps_r    = (const float*)d_in[19];
    const float* hw1      = (const float*)d_in[20];
    const float* hb1      = (const float*)d_in[21];
    const float* hw2      = (const float*)d_in[22];
    const float* hb2      = (const float*)d_in[23];
    const float* hw3      = (const float*)d_in[24];
    const float* hb3      = (const float*)d_in[25];
    const int*   edge_index = (const int*)d_in[26];
    const int*   batch    = (const int*)d_in[27];

    const int* src = edge_index;
    const int* dst = edge_index + N_EDGES;

    float* pre   = (float*)sym_addr(g_pre);
    float* tmp   = (float*)sym_addr(g_tmp);
    float* hA    = (float*)sym_addr(g_hA);
    float* hB    = (float*)sym_addr(g_hB);
    int*   deg   = (int*)sym_addr(g_deg);
    int*   rowptr= (int*)sym_addr(g_rowptr);
    int*   cursor= (int*)sym_addr(g_cursor);
    int*   srcp  = (int*)sym_addr(g_srcp);
    float4* eap  = (float4*)sym_addr(g_eap);
    int*   gptr  = (int*)sym_addr(g_gptr);
    float* stats = (float*)sym_addr(g_stats);
    float* pool  = (float*)sym_addr(g_pool);
    float* z2    = (float*)sym_addr(g_z2);
    __nv_bfloat16* whi = (__nv_bfloat16*)sym_addr(g_whi);
    __nv_bfloat16* wlo = (__nv_bfloat16*)sym_addr(g_wlo);
    float* out   = (float*)d_out;

    cudaFuncSetAttribute(gemm_mlp_k, cudaFuncAttributeMaxDynamicSharedMemorySize, SM_TOTAL);

    const int SLOT = 128 * 128;

    // Launch order matters for ncu (-s 5 -c 1 captures launch #6 = layer-0 gemm_mlp).
    // 1: init (zero deg + stats, split weights)
    init_k<<<(12 * 16384 + 255) / 256, 256>>>(w1_0, w2_0, w1, w2, hw1, hw2, whi, wlo, deg, stats);
    // 2-4: CSR
    count_deg_k<<<(N_EDGES + 255) / 256, 256>>>(dst, deg);
    scan_csr_k<<<1, 1024>>>(deg, rowptr, cursor);
    fill_csr_k<<<(N_EDGES + 255) / 256, 256>>>(src, dst, edge_attr, cursor, srcp, eap);

    const int GB_N = (N_NODES + 63) / 64;
    const int GB_G = (N_GRAPHS + 63) / 64;
    const int BN_BLOCKS = (int)(((size_t)N_NODES * 32 + 255) / 256);

    // 5: layer-0 aggregate
    aggregate11_k<<<(N_NODES + 3) / 4, 128>>>(x, eap, e_w0, e_b0, eps0, srcp, rowptr, pre);
    // 6: layer-0 fused MLP  <-- ncu capture target
    gemm_mlp_k<<<GB_N, 256, SM_TOTAL>>>(pre, N_NODES, IN_DIM, IN_DIM,
                                        whi + 0 * SLOT, wlo + 0 * SLOT, b1_0,
                                        whi + 1 * SLOT, wlo + 1 * SLOT, b2_0,
                                        tmp, 0, stats, stats + HID, 1);
    bn_relu_res_k<<<BN_BLOCKS, 256>>>((const float4*)tmp, stats, gamma0, beta0,
                                      nullptr, (float4*)hA, N_NODES);

    // ---- layers 1..4 ----
    float* cur = hA;
    float* nxt = hB;
    for (int i = 0; i < N_REST; i++) {
        float* st = stats + (size_t)(1 + i) * 2 * HID;
        aggregate128_k<<<(N_NODES + 1) / 2, 256>>>(cur, eap, e_w + (size_t)i * 3 * HID,
                                                   e_b + (size_t)i * HID, eps_r + i,
                                                   srcp, rowptr, pre);
        gemm_mlp_k<<<GB_N, 256, SM_TOTAL>>>(pre, N_NODES, HID, HID,
                                            whi + (2 + i) * SLOT, wlo + (2 + i) * SLOT,
                                            b1 + (size_t)i * HID,
                                            whi + (6 + i) * SLOT, wlo + (6 + i) * SLOT,
                                            b2 + (size_t)i * HID,
                                            tmp, 0, st, st + HID, 8);
        bn_relu_res_k<<<BN_BLOCKS, 256>>>((const float4*)tmp, st,
                                          gamma + (size_t)i * HID, beta + (size_t)i * HID,
                                          (const float4*)cur, (float4*)nxt, N_NODES);
        float* t = cur; cur = nxt; nxt = t;
    }

    // ---- pooling ----
    graph_ptr_k<<<(N_GRAPHS + 1 + 127) / 128, 128>>>(batch, gptr);
    pool_k<<<N_GRAPHS, HID>>>(cur, gptr, pool);

    // ---- head ----
    gemm_mlp_k<<<GB_G, 256, SM_TOTAL>>>(pool, N_GRAPHS, HID, HID,
                                        whi + 10 * SLOT, wlo + 10 * SLOT, hb1,
                                        whi + 11 * SLOT, wlo + 11 * SLOT, hb2,
                                        z2, 1, nullptr, nullptr, 8);
    head_out_k<<<N_GRAPHS, HID>>>(z2, hw3, hb3, out);
}

// round 6
// speedup vs baseline: 2.2272x; 1.1326x over previous
#include <cuda_runtime.h>
#include <cuda_fp16.h>
#include <cstdint>

#define N_NODES 100000
#define N_EDGES 600000
#define N_GRAPHS 5000
#define IN_DIM 11
#define HID 128
#define EDGE_DIM 3
#define N_REST 4
#define BN_EPS 1e-5f

// ======================= PTX helpers (baseline sm_80+ ISA only) =======================
__device__ __forceinline__ uint32_t smem_u32(const void* p) {
    uint32_t a;
    asm("{ .reg .u64 t; cvta.to.shared.u64 t, %1; cvt.u32.u64 %0, t; }" : "=r"(a) : "l"(p));
    return a;
}

#define LDSM_X4(r0, r1, r2, r3, addr)                                            \
    asm volatile("ldmatrix.sync.aligned.m8n8.x4.shared.b16 {%0,%1,%2,%3}, [%4];" \
                 : "=r"(r0), "=r"(r1), "=r"(r2), "=r"(r3) : "r"(addr))

#define LDSM_X4T(r0, r1, r2, r3, addr)                                                 \
    asm volatile("ldmatrix.sync.aligned.m8n8.x4.trans.shared.b16 {%0,%1,%2,%3}, [%4];" \
                 : "=r"(r0), "=r"(r1), "=r"(r2), "=r"(r3) : "r"(addr))

__device__ __forceinline__ void mma_fp16(float* c, const uint32_t* a, const uint32_t* b) {
    asm volatile(
        "mma.sync.aligned.m16n8k16.row.col.f32.f16.f16.f32 "
        "{%0,%1,%2,%3}, {%4,%5,%6,%7}, {%8,%9}, {%0,%1,%2,%3};"
        : "+f"(c[0]), "+f"(c[1]), "+f"(c[2]), "+f"(c[3])
        : "r"(a[0]), "r"(a[1]), "r"(a[2]), "r"(a[3]), "r"(b[0]), "r"(b[1]));
}

// ======================= scratch =======================
__device__ float g_pre[(size_t)N_NODES * HID];
__device__ float g_tmp[(size_t)N_NODES * HID];
__device__ float g_hA[(size_t)N_NODES * HID];
__device__ float g_hB[(size_t)N_NODES * HID];

__device__ int g_deg[N_NODES];
__device__ int g_rowptr[N_NODES + 1];
__device__ int g_cursor[N_NODES + 1];
__device__ int g_srcp[N_EDGES];
__device__ float4 g_eap[N_EDGES];
__device__ int g_gptr[N_GRAPHS + 1];

__device__ float g_stats[5 * 2 * HID];          // per-layer (sum, sumsq)
__device__ float g_pool[(size_t)N_GRAPHS * HID];
__device__ float g_z2[(size_t)N_GRAPHS * HID];

// pre-rounded fp16 weights: 12 slots of [128][128] (slot0 = w1_0 zero-padded past row 10)
__device__ __half g_wh[12 * 128 * 128];

// ======================= init: zero deg + stats, round weights =======================
__global__ void init_k(const float* __restrict__ w1_0, const float* __restrict__ w2_0,
                       const float* __restrict__ w1, const float* __restrict__ w2,
                       const float* __restrict__ hw1, const float* __restrict__ hw2,
                       __half* __restrict__ wh,
                       int* __restrict__ deg, float* __restrict__ stats) {
    int idx = blockIdx.x * 256 + threadIdx.x;
    if (idx < N_NODES) deg[idx] = 0;
    if (idx < 5 * 2 * HID) stats[idx] = 0.f;
    if (idx >= 12 * 16384) return;
    int slot = idx >> 14, off = idx & 16383;
    int k = off >> 7;
    float v = 0.f;
    if (slot == 0) { if (k < IN_DIM) v = w1_0[off]; }
    else if (slot == 1) v = w2_0[off];
    else if (slot < 6) v = w1[(slot - 2) * 16384 + off];
    else if (slot < 10) v = w2[(slot - 6) * 16384 + off];
    else if (slot == 10) v = hw1[off];
    else v = hw2[off];
    wh[idx] = __float2half_rn(v);
}

// ======================= CSR build =======================
__global__ void count_deg_k(const int* __restrict__ dst, int* __restrict__ deg) {
    int e = blockIdx.x * blockDim.x + threadIdx.x;
    if (e < N_EDGES) atomicAdd(&deg[dst[e]], 1);
}

__global__ void scan_csr_k(const int* __restrict__ deg, int* __restrict__ rowptr,
                           int* __restrict__ cursor) {
    __shared__ int warpS[32];
    __shared__ int warpOff[32];
    __shared__ int carryS;
    int tid = threadIdx.x, lane = tid & 31, w = tid >> 5;
    if (tid == 0) { carryS = 0; rowptr[0] = 0; }
    __syncthreads();
    for (int base = 0; base < N_NODES; base += 1024) {
        int i = base + tid;
        int v = (i < N_NODES) ? deg[i] : 0;
        int x = v;
        #pragma unroll
        for (int o = 1; o < 32; o <<= 1) {
            int t = __shfl_up_sync(0xFFFFFFFFu, x, o);
            if (lane >= o) x += t;
        }
        if (lane == 31) warpS[w] = x;
        __syncthreads();
        if (w == 0) {
            int y = warpS[lane];
            int z = y;
            #pragma unroll
            for (int o = 1; o < 32; o <<= 1) {
                int t = __shfl_up_sync(0xFFFFFFFFu, z, o);
                if (lane >= o) z += t;
            }
            warpOff[lane] = z - y;
            if (lane == 31) warpS[0] = z;
        }
        __syncthreads();
        int c = carryS;
        int incl = x + warpOff[w];
        if (i < N_NODES) {
            rowptr[i + 1] = c + incl;
            cursor[i] = c + incl - v;
        }
        int chunkTot = warpS[0];
        __syncthreads();
        if (tid == 0) carryS = c + chunkTot;
        __syncthreads();
    }
}

__global__ void fill_csr_k(const int* __restrict__ src, const int* __restrict__ dst,
                           const float* __restrict__ ea, int* __restrict__ cursor,
                           int* __restrict__ srcp, float4* __restrict__ eap) {
    int e = blockIdx.x * blockDim.x + threadIdx.x;
    if (e < N_EDGES) {
        int p = atomicAdd(&cursor[dst[e]], 1);
        srcp[p] = src[e];
        float4 t;
        t.x = ea[(size_t)e * 3];
        t.y = ea[(size_t)e * 3 + 1];
        t.z = ea[(size_t)e * 3 + 2];
        t.w = 0.f;
        eap[p] = t;
    }
}

// ======================= aggregation =======================
__global__ void aggregate11_k(const float* __restrict__ h, const float4* __restrict__ eap,
                              const float* __restrict__ ew, const float* __restrict__ eb,
                              const float* __restrict__ epsp,
                              const int* __restrict__ srcp, const int* __restrict__ rowptr,
                              float* __restrict__ out) {
    int n = blockIdx.x * 4 + (threadIdx.x >> 5);
    int d = threadIdx.x & 31;
    if (n >= N_NODES || d >= IN_DIM) return;
    float w0 = ew[d], w1 = ew[IN_DIM + d], w2 = ew[2 * IN_DIM + d], b = eb[d];
    int s0 = rowptr[n], s1 = rowptr[n + 1];
    float acc = 0.f;
    int p = s0;
    for (; p + 2 <= s1; p += 2) {
        int i0 = srcp[p], i1 = srcp[p + 1];
        float4 e0 = eap[p], e1 = eap[p + 1];
        float gg0 = h[(size_t)i0 * IN_DIM + d];
        float gg1 = h[(size_t)i1 * IN_DIM + d];
        acc += fmaxf(gg0 + e0.x * w0 + e0.y * w1 + e0.z * w2 + b, 0.f);
        acc += fmaxf(gg1 + e1.x * w0 + e1.y * w1 + e1.z * w2 + b, 0.f);
    }
    for (; p < s1; p++) {
        int i0 = srcp[p];
        float4 e0 = eap[p];
        acc += fmaxf(h[(size_t)i0 * IN_DIM + d] + e0.x * w0 + e0.y * w1 + e0.z * w2 + b, 0.f);
    }
    float eps = *epsp;
    out[(size_t)n * IN_DIM + d] = (1.f + eps) * h[(size_t)n * IN_DIM + d] + acc;
}

__global__ void __launch_bounds__(256)
aggregate128_k(const float* __restrict__ h, const float4* __restrict__ eap,
               const float* __restrict__ ew, const float* __restrict__ eb,
               const float* __restrict__ epsp,
               const int* __restrict__ srcp, const int* __restrict__ rowptr,
               float* __restrict__ out) {
    int n = blockIdx.x * 2 + (threadIdx.x >> 7);
    int d = threadIdx.x & 127;
    if (n >= N_NODES) return;
    float w0 = ew[d], w1 = ew[HID + d], w2 = ew[2 * HID + d], b = eb[d];
    int s0 = rowptr[n], s1 = rowptr[n + 1];
    float acc = 0.f;
    int p = s0;
    for (; p + 4 <= s1; p += 4) {
        int i0 = srcp[p], i1 = srcp[p + 1], i2 = srcp[p + 2], i3 = srcp[p + 3];
        float4 e0 = eap[p], e1 = eap[p + 1], e2 = eap[p + 2], e3 = eap[p + 3];
        float gg0 = h[(size_t)i0 * HID + d];
        float gg1 = h[(size_t)i1 * HID + d];
        float gg2 = h[(size_t)i2 * HID + d];
        float gg3 = h[(size_t)i3 * HID + d];
        acc += fmaxf(gg0 + e0.x * w0 + e0.y * w1 + e0.z * w2 + b, 0.f);
        acc += fmaxf(gg1 + e1.x * w0 + e1.y * w1 + e1.z * w2 + b, 0.f);
        acc += fmaxf(gg2 + e2.x * w0 + e2.y * w1 + e2.z * w2 + b, 0.f);
        acc += fmaxf(gg3 + e3.x * w0 + e3.y * w1 + e3.z * w2 + b, 0.f);
    }
    for (; p < s1; p++) {
        int i0 = srcp[p];
        float4 e0 = eap[p];
        acc += fmaxf(h[(size_t)i0 * HID + d] + e0.x * w0 + e0.y * w1 + e0.z * w2 + b, 0.f);
    }
    float eps = *epsp;
    out[(size_t)n * HID + d] = (1.f + eps) * h[(size_t)n * HID + d] + acc;
}

// ======================= fused 2-GEMM MLP (fp16 2-pass, M=64 tiles, 3 CTAs/SM) =======================
// C[M,128] = act2( relu(A[M,Kact] @ W1 + b1) @ W2 + b2 ), optional BN stats.
// A split into fp16 hi/lo (2 mma passes); W pre-rounded to fp16.
#define APAD 136
#define SX_HI   0
#define SX_LO   17408
#define SY      34816
#define S_B1    69632
#define S_B2    70144
#define S_STAT  70656
#define SM_TOTAL (S_STAT + 2048)
#define STG_PITCH 130

__global__ void __launch_bounds__(256, 3)
gemm_mlp_k(const float* __restrict__ A, int M, int Kact, int Apitch,
           const __half* __restrict__ W1, const float* __restrict__ b1,
           const __half* __restrict__ W2, const float* __restrict__ b2,
           float* __restrict__ C, int do_relu2,
           float* __restrict__ ssum, float* __restrict__ ssq, int nsteps1) {
    extern __shared__ __align__(16) char smem[];
    __half* aHi = (__half*)(smem + SX_HI);
    __half* aLo = (__half*)(smem + SX_LO);
    __half* wS  = (__half*)(smem + SY);
    float* b1S = (float*)(smem + S_B1);
    float* b2S = (float*)(smem + S_B2);
    float* statS = (float*)(smem + S_STAT);

    int tid = threadIdx.x;
    int lane = tid & 31;
    int wid = tid >> 5;
    int rowBase = blockIdx.x * 64;
    int kmax1 = nsteps1 << 4;

    if (tid < HID) { b1S[tid] = b1[tid]; b2S[tid] = b2[tid]; }

    // ---- load + split A [64 x kmax1] into fp16 hi/lo ----
    if (Kact == HID) {
        for (int idx = tid; idx < 64 * 32; idx += 256) {
            int r = idx >> 5, seg = idx & 31;
            int gr = rowBase + r;
            float4 v = (gr < M) ? __ldg((const float4*)(A + (size_t)gr * Apitch) + seg)
                                : make_float4(0.f, 0.f, 0.f, 0.f);
            __half h0 = __float2half_rn(v.x), h1 = __float2half_rn(v.y);
            __half h2 = __float2half_rn(v.z), h3 = __float2half_rn(v.w);
            __half l0 = __float2half_rn(v.x - __half2float(h0));
            __half l1 = __float2half_rn(v.y - __half2float(h1));
            __half l2 = __float2half_rn(v.z - __half2float(h2));
            __half l3 = __float2half_rn(v.w - __half2float(h3));
            __half2* ph = (__half2*)&aHi[r * APAD + seg * 4];
            __half2* pl = (__half2*)&aLo[r * APAD + seg * 4];
            ph[0] = __halves2half2(h0, h1); ph[1] = __halves2half2(h2, h3);
            pl[0] = __halves2half2(l0, l1); pl[1] = __halves2half2(l2, l3);
        }
    } else {
        for (int idx = tid; idx < 64 * 16; idx += 256) {
            int r = idx >> 4, k = idx & 15;
            int gr = rowBase + r;
            float a = (gr < M && k < Kact) ? __ldg(A + (size_t)gr * Apitch + k) : 0.f;
            __half h = __float2half_rn(a);
            aHi[r * APAD + k] = h;
            aLo[r * APAD + k] = __float2half_rn(a - __half2float(h));
        }
    }
    // ---- load W1 (fp16): kmax1 rows x 128 ----
    for (int idx = tid; idx < kmax1 * 16; idx += 256) {
        int k = idx >> 4, seg = idx & 15;
        *(uint4*)&wS[k * APAD + seg * 8] = __ldg((const uint4*)(W1 + k * HID) + seg);
    }
    __syncthreads();

    // ---- warp tiling: 8 warps = 2 (rows) x 4 (cols); warp tile 32 x 32 ----
    int warpR = (wid >> 2) << 5;
    int warpC = (wid & 3) << 5;
    uint32_t aBase = smem_u32(aHi);
    uint32_t wBase = smem_u32(wS);
    float acc[2][4][4];

    #pragma unroll
    for (int m = 0; m < 2; m++)
        #pragma unroll
        for (int j = 0; j < 4; j++)
            #pragma unroll
            for (int q = 0; q < 4; q++) acc[m][j][q] = 0.f;

    // ================= pass 1 =================
    for (int s = 0; s < nsteps1; s++) {
        int k0 = s << 4;
        uint32_t aAddr = aBase +
            ((uint32_t)((warpR + (lane & 15)) * APAD + k0 + ((lane >> 4) << 3)) << 1);
        uint32_t ah0[4], ah1[4], al0[4], al1[4];
        LDSM_X4(ah0[0], ah0[1], ah0[2], ah0[3], aAddr);
        LDSM_X4(ah1[0], ah1[1], ah1[2], ah1[3], aAddr + 16 * APAD * 2);
        LDSM_X4(al0[0], al0[1], al0[2], al0[3], aAddr + (SX_LO - SX_HI));
        LDSM_X4(al1[0], al1[1], al1[2], al1[3], aAddr + (SX_LO - SX_HI) + 16 * APAD * 2);

        uint32_t bAddr = wBase +
            ((uint32_t)((k0 + (lane & 7) + ((lane >> 3) & 1) * 8) * APAD +
                        warpC + ((lane >> 4) << 3)) << 1);
        uint32_t bf[4][2];
        #pragma unroll
        for (int pp = 0; pp < 2; pp++) {
            uint32_t r0, r1, r2, r3;
            LDSM_X4T(r0, r1, r2, r3, bAddr + pp * 32);
            bf[2 * pp][0] = r0; bf[2 * pp][1] = r1;
            bf[2 * pp + 1][0] = r2; bf[2 * pp + 1][1] = r3;
        }
        #pragma unroll
        for (int j = 0; j < 4; j++) {
            mma_fp16(acc[0][j], ah0, bf[j]);
            mma_fp16(acc[1][j], ah1, bf[j]);
            mma_fp16(acc[0][j], al0, bf[j]);
            mma_fp16(acc[1][j], al1, bf[j]);
        }
    }
    __syncthreads();

    // ---- T1 = relu(acc + b1) -> split into X region; load W2 into Y ----
    #pragma unroll
    for (int m = 0; m < 2; m++) {
        #pragma unroll
        for (int j = 0; j < 4; j++) {
            #pragma unroll
            for (int q = 0; q < 4; q++) {
                int row = warpR + m * 16 + (lane >> 2) + ((q >> 1) << 3);
                int col = warpC + j * 8 + ((lane & 3) << 1) + (q & 1);
                float t = fmaxf(acc[m][j][q] + b1S[col], 0.f);
                __half h = __float2half_rn(t);
                aHi[row * APAD + col] = h;
                aLo[row * APAD + col] = __float2half_rn(t - __half2float(h));
            }
        }
    }
    for (int idx = tid; idx < 128 * 16; idx += 256) {
        int k = idx >> 4, seg = idx & 15;
        *(uint4*)&wS[k * APAD + seg * 8] = __ldg((const uint4*)(W2 + k * HID) + seg);
    }
    __syncthreads();

    // ================= pass 2 (K = 128) =================
    #pragma unroll
    for (int m = 0; m < 2; m++)
        #pragma unroll
        for (int j = 0; j < 4; j++)
            #pragma unroll
            for (int q = 0; q < 4; q++) acc[m][j][q] = 0.f;

    for (int s = 0; s < 8; s++) {
        int k0 = s << 4;
        uint32_t aAddr = aBase +
            ((uint32_t)((warpR + (lane & 15)) * APAD + k0 + ((lane >> 4) << 3)) << 1);
        uint32_t ah0[4], ah1[4], al0[4], al1[4];
        LDSM_X4(ah0[0], ah0[1], ah0[2], ah0[3], aAddr);
        LDSM_X4(ah1[0], ah1[1], ah1[2], ah1[3], aAddr + 16 * APAD * 2);
        LDSM_X4(al0[0], al0[1], al0[2], al0[3], aAddr + (SX_LO - SX_HI));
        LDSM_X4(al1[0], al1[1], al1[2], al1[3], aAddr + (SX_LO - SX_HI) + 16 * APAD * 2);

        uint32_t bAddr = wBase +
            ((uint32_t)((k0 + (lane & 7) + ((lane >> 3) & 1) * 8) * APAD +
                        warpC + ((lane >> 4) << 3)) << 1);
        uint32_t bf[4][2];
        #pragma unroll
        for (int pp = 0; pp < 2; pp++) {
            uint32_t r0, r1, r2, r3;
            LDSM_X4T(r0, r1, r2, r3, bAddr + pp * 32);
            bf[2 * pp][0] = r0; bf[2 * pp][1] = r1;
            bf[2 * pp + 1][0] = r2; bf[2 * pp + 1][1] = r3;
        }
        #pragma unroll
        for (int j = 0; j < 4; j++) {
            mma_fp16(acc[0][j], ah0, bf[j]);
            mma_fp16(acc[1][j], ah1, bf[j]);
            mma_fp16(acc[0][j], al0, bf[j]);
            mma_fp16(acc[1][j], al1, bf[j]);
        }
    }
    __syncthreads();

    // ---- epilogue: stage to smem (reuse X region) ----
    float* stg = (float*)smem;
    #pragma unroll
    for (int m = 0; m < 2; m++) {
        #pragma unroll
        for (int j = 0; j < 4; j++) {
            int row = warpR + m * 16 + (lane >> 2);
            int col = warpC + j * 8 + ((lane & 3) << 1);
            stg[row * STG_PITCH + col]       = acc[m][j][0];
            stg[row * STG_PITCH + col + 1]   = acc[m][j][1];
            stg[(row + 8) * STG_PITCH + col]     = acc[m][j][2];
            stg[(row + 8) * STG_PITCH + col + 1] = acc[m][j][3];
        }
    }
    __syncthreads();

    // ---- coalesced store + bias2/relu2 + fused BN stats ----
    {
        int c = tid & 127, hh = tid >> 7;
        float bia = b2S[c];
        float s0 = 0.f, q0 = 0.f;
        #pragma unroll 4
        for (int j = 0; j < 32; j++) {
            int r = hh * 32 + j;
            int gr = rowBase + r;
            if (gr < M) {
                float v = stg[r * STG_PITCH + c] + bia;
                if (do_relu2) v = fmaxf(v, 0.f);
                C[(size_t)gr * HID + c] = v;
                s0 += v;
                q0 += v * v;
            }
        }
        if (ssum) {
            statS[hh * 128 + c] = s0;
            statS[256 + hh * 128 + c] = q0;
            __syncthreads();
            if (tid < 128) {
                atomicAdd(&ssum[tid], statS[tid] + statS[128 + tid]);
                atomicAdd(&ssq[tid], statS[256 + tid] + statS[384 + tid]);
            }
        }
    }
}

// ======================= BN + relu + optional residual (float4) =======================
__global__ void bn_relu_res_k(const float4* __restrict__ tmp, const float* __restrict__ stats,
                              const float* __restrict__ gamma, const float* __restrict__ beta,
                              const float4* __restrict__ res, float4* __restrict__ out,
                              int n_rows) {
    size_t i = (size_t)blockIdx.x * blockDim.x + threadIdx.x;
    size_t total = (size_t)n_rows * 32;
    if (i >= total) return;
    int d = ((int)(i & 31)) << 2;
    float invN = 1.f / (float)n_rows;
    float4 t = tmp[i];
    float4 o;
    {
        float mu = stats[d] * invN;
        float var = stats[HID + d] * invN - mu * mu;
        o.x = fmaxf((t.x - mu) * rsqrtf(var + BN_EPS) * gamma[d] + beta[d], 0.f);
    }
    {
        float mu = stats[d + 1] * invN;
        float var = stats[HID + d + 1] * invN - mu * mu;
        o.y = fmaxf((t.y - mu) * rsqrtf(var + BN_EPS) * gamma[d + 1] + beta[d + 1], 0.f);
    }
    {
        float mu = stats[d + 2] * invN;
        float var = stats[HID + d + 2] * invN - mu * mu;
        o.z = fmaxf((t.z - mu) * rsqrtf(var + BN_EPS) * gamma[d + 2] + beta[d + 2], 0.f);
    }
    {
        float mu = stats[d + 3] * invN;
        float var = stats[HID + d + 3] * invN - mu * mu;
        o.w = fmaxf((t.w - mu) * rsqrtf(var + BN_EPS) * gamma[d + 3] + beta[d + 3], 0.f);
    }
    if (res) {
        float4 r = res[i];
        o.x += r.x; o.y += r.y; o.z += r.z; o.w += r.w;
    }
    out[i] = o;
}

// ======================= pooling =======================
__global__ void graph_ptr_k(const int* __restrict__ batch, int* __restrict__ gptr) {
    int g = blockIdx.x * blockDim.x + threadIdx.x;
    if (g > N_GRAPHS) return;
    int lo = 0, hi = N_NODES;
    while (lo < hi) {
        int mid = (lo + hi) >> 1;
        if (batch[mid] < g) lo = mid + 1; else hi = mid;
    }
    gptr[g] = lo;
}
__global__ void pool_k(const float* __restrict__ h, const int* __restrict__ gptr,
                       float* __restrict__ pooled) {
    int g = blockIdx.x;
    int d = threadIdx.x;
    int a = gptr[g], b = gptr[g + 1];
    float acc = 0.f;
    for (int n = a; n < b; n++) acc += h[(size_t)n * HID + d];
    int cnt = b - a;
    float c = (float)(cnt > 1 ? cnt : 1);
    pooled[(size_t)g * HID + d] = acc / c;
}

// ======================= head final dot =======================
__global__ void head_out_k(const float* __restrict__ z, const float* __restrict__ w,
                           const float* __restrict__ b, float* __restrict__ out) {
    int g = blockIdx.x;
    int t = threadIdx.x; // 128
    float v = z[(size_t)g * HID + t] * w[t];
    #pragma unroll
    for (int off = 16; off; off >>= 1) v += __shfl_down_sync(0xFFFFFFFFu, v, off);
    __shared__ float s[4];
    if ((t & 31) == 0) s[t >> 5] = v;
    __syncthreads();
    if (t == 0) out[g] = s[0] + s[1] + s[2] + s[3] + b[0];
}

// ======================= host =======================
static void* sym_addr(const void* sym) {
    void* p = nullptr;
    cudaGetSymbolAddress(&p, sym);
    return p;
}

extern "C" void kernel_launch(void* const* d_in, const int* in_sizes, int n_in,
                              void* d_out, int out_size) {
    const float* x        = (const float*)d_in[0];
    const float* edge_attr= (const float*)d_in[1];
    const float* e_w0     = (const float*)d_in[2];
    const float* e_b0     = (const float*)d_in[3];
    const float* w1_0     = (const float*)d_in[4];
    const float* b1_0     = (const float*)d_in[5];
    const float* w2_0     = (const float*)d_in[6];
    const float* b2_0     = (const float*)d_in[7];
    const float* gamma0   = (const float*)d_in[8];
    const float* beta0    = (const float*)d_in[9];
    const float* eps0     = (const float*)d_in[10];
    const float* e_w      = (const float*)d_in[11];
    const float* e_b      = (const float*)d_in[12];
    const float* w1       = (const float*)d_in[13];
    const float* b1       = (const float*)d_in[14];
    const float* w2       = (const float*)d_in[15];
    const float* b2       = (const float*)d_in[16];
    const float* gamma    = (const float*)d_in[17];
    const float* beta     = (const float*)d_in[18];
    const float* eps_r    = (const float*)d_in[19];
    const float* hw1      = (const float*)d_in[20];
    const float* hb1      = (const float*)d_in[21];
    const float* hw2      = (const float*)d_in[22];
    const float* hb2      = (const float*)d_in[23];
    const float* hw3      = (const float*)d_in[24];
    const float* hb3      = (const float*)d_in[25];
    const int*   edge_index = (const int*)d_in[26];
    const int*   batch    = (const int*)d_in[27];

    const int* src = edge_index;
    const int* dst = edge_index + N_EDGES;

    float* pre   = (float*)sym_addr(g_pre);
    float* tmp   = (float*)sym_addr(g_tmp);
    float* hA    = (float*)sym_addr(g_hA);
    float* hB    = (float*)sym_addr(g_hB);
    int*   deg   = (int*)sym_addr(g_deg);
    int*   rowptr= (int*)sym_addr(g_rowptr);
    int*   cursor= (int*)sym_addr(g_cursor);
    int*   srcp  = (int*)sym_addr(g_srcp);
    float4* eap  = (float4*)sym_addr(g_eap);
    int*   gptr  = (int*)sym_addr(g_gptr);
    float* stats = (float*)sym_addr(g_stats);
    float* pool  = (float*)sym_addr(g_pool);
    float* z2    = (float*)sym_addr(g_z2);
    __half* wh   = (__half*)sym_addr(g_wh);
    float* out   = (float*)d_out;

    cudaFuncSetAttribute(gemm_mlp_k, cudaFuncAttributeMaxDynamicSharedMemorySize, SM_TOTAL);

    const int SLOT = 128 * 128;

    // 1: init (zero deg + stats, round weights)
    init_k<<<(12 * 16384 + 255) / 256, 256>>>(w1_0, w2_0, w1, w2, hw1, hw2, wh, deg, stats);
    // 2-4: CSR
    count_deg_k<<<(N_EDGES + 255) / 256, 256>>>(dst, deg);
    scan_csr_k<<<1, 1024>>>(deg, rowptr, cursor);
    fill_csr_k<<<(N_EDGES + 255) / 256, 256>>>(src, dst, edge_attr, cursor, srcp, eap);

    const int GB_N = (N_NODES + 63) / 64;
    const int GB_G = (N_GRAPHS + 63) / 64;
    const int BN_BLOCKS = (int)(((size_t)N_NODES * 32 + 255) / 256);

    // 5: layer-0 aggregate
    aggregate11_k<<<(N_NODES + 3) / 4, 128>>>(x, eap, e_w0, e_b0, eps0, srcp, rowptr, pre);
    // 6: layer-0 fused MLP
    gemm_mlp_k<<<GB_N, 256, SM_TOTAL>>>(pre, N_NODES, IN_DIM, IN_DIM,
                                        wh + 0 * SLOT, b1_0,
                                        wh + 1 * SLOT, b2_0,
                                        tmp, 0, stats, stats + HID, 1);
    bn_relu_res_k<<<BN_BLOCKS, 256>>>((const float4*)tmp, stats, gamma0, beta0,
                                      nullptr, (float4*)hA, N_NODES);

    // ---- layers 1..4 ----
    float* cur = hA;
    float* nxt = hB;
    for (int i = 0; i < N_REST; i++) {
        float* st = stats + (size_t)(1 + i) * 2 * HID;
        aggregate128_k<<<(N_NODES + 1) / 2, 256>>>(cur, eap, e_w + (size_t)i * 3 * HID,
                                                   e_b + (size_t)i * HID, eps_r + i,
                                                   srcp, rowptr, pre);
        gemm_mlp_k<<<GB_N, 256, SM_TOTAL>>>(pre, N_NODES, HID, HID,
                                            wh + (2 + i) * SLOT, b1 + (size_t)i * HID,
                                            wh + (6 + i) * SLOT, b2 + (size_t)i * HID,
                                            tmp, 0, st, st + HID, 8);
        bn_relu_res_k<<<BN_BLOCKS, 256>>>((const float4*)tmp, st,
                                          gamma + (size_t)i * HID, beta + (size_t)i * HID,
                                          (const float4*)cur, (float4*)nxt, N_NODES);
        float* t = cur; cur = nxt; nxt = t;
    }

    // ---- pooling ----
    graph_ptr_k<<<(N_GRAPHS + 1 + 127) / 128, 128>>>(batch, gptr);
    pool_k<<<N_GRAPHS, HID>>>(cur, gptr, pool);

    // ---- head ----
    gemm_mlp_k<<<GB_G, 256, SM_TOTAL>>>(pool, N_GRAPHS, HID, HID,
                                        wh + 10 * SLOT, hb1,
                                        wh + 11 * SLOT, hb2,
                                        z2, 1, nullptr, nullptr, 8);
    head_out_k<<<N_GRAPHS, HID>>>(z2, hw3, hb3, out);
}

// round 7
// speedup vs baseline: 3.0665x; 1.3769x over previous
#include <cuda_runtime.h>
#include <cuda_fp16.h>
#include <cstdint>

#define N_NODES 100000
#define N_EDGES 600000
#define N_GRAPHS 5000
#define IN_DIM 11
#define HID 128
#define EDGE_DIM 3
#define N_REST 4
#define BN_EPS 1e-5f

// ======================= PTX helpers (baseline sm_80+ ISA only) =======================
__device__ __forceinline__ uint32_t smem_u32(const void* p) {
    uint32_t a;
    asm("{ .reg .u64 t; cvta.to.shared.u64 t, %1; cvt.u32.u64 %0, t; }" : "=r"(a) : "l"(p));
    return a;
}

#define LDSM_X4(r0, r1, r2, r3, addr)                                            \
    asm volatile("ldmatrix.sync.aligned.m8n8.x4.shared.b16 {%0,%1,%2,%3}, [%4];" \
                 : "=r"(r0), "=r"(r1), "=r"(r2), "=r"(r3) : "r"(addr))

#define LDSM_X4T(r0, r1, r2, r3, addr)                                                 \
    asm volatile("ldmatrix.sync.aligned.m8n8.x4.trans.shared.b16 {%0,%1,%2,%3}, [%4];" \
                 : "=r"(r0), "=r"(r1), "=r"(r2), "=r"(r3) : "r"(addr))

__device__ __forceinline__ void mma_fp16(float* c, const uint32_t* a, const uint32_t* b) {
    asm volatile(
        "mma.sync.aligned.m16n8k16.row.col.f32.f16.f16.f32 "
        "{%0,%1,%2,%3}, {%4,%5,%6,%7}, {%8,%9}, {%0,%1,%2,%3};"
        : "+f"(c[0]), "+f"(c[1]), "+f"(c[2]), "+f"(c[3])
        : "r"(a[0]), "r"(a[1]), "r"(a[2]), "r"(a[3]), "r"(b[0]), "r"(b[1]));
}

// ======================= scratch =======================
__device__ float g_pre[(size_t)N_NODES * HID];
__device__ float g_tmp[(size_t)N_NODES * HID];
__device__ float g_hA[(size_t)N_NODES * HID];
__device__ float g_hB[(size_t)N_NODES * HID];

__device__ int g_deg[N_NODES];
__device__ int g_rowptr[N_NODES + 1];
__device__ int g_cursor[N_NODES + 1];
__device__ int g_srcp[N_EDGES];
__device__ float4 g_eap[N_EDGES];
__device__ int g_gptr[N_GRAPHS + 1];

__device__ float g_stats[5 * 2 * HID];          // per-layer (sum, sumsq)
__device__ float g_pool[(size_t)N_GRAPHS * HID];
__device__ float g_z2[(size_t)N_GRAPHS * HID];

// pre-rounded fp16 weights: 12 slots of [128][128] (slot0 = w1_0 zero-padded past row 10)
__device__ __half g_wh[12 * 128 * 128];

// ======================= init: zero deg + stats, round weights =======================
__global__ void init_k(const float* __restrict__ w1_0, const float* __restrict__ w2_0,
                       const float* __restrict__ w1, const float* __restrict__ w2,
                       const float* __restrict__ hw1, const float* __restrict__ hw2,
                       __half* __restrict__ wh,
                       int* __restrict__ deg, float* __restrict__ stats) {
    int idx = blockIdx.x * 256 + threadIdx.x;
    if (idx < N_NODES) deg[idx] = 0;
    if (idx < 5 * 2 * HID) stats[idx] = 0.f;
    if (idx >= 12 * 16384) return;
    int slot = idx >> 14, off = idx & 16383;
    int k = off >> 7;
    float v = 0.f;
    if (slot == 0) { if (k < IN_DIM) v = w1_0[off]; }
    else if (slot == 1) v = w2_0[off];
    else if (slot < 6) v = w1[(slot - 2) * 16384 + off];
    else if (slot < 10) v = w2[(slot - 6) * 16384 + off];
    else if (slot == 10) v = hw1[off];
    else v = hw2[off];
    wh[idx] = __float2half_rn(v);
}

// ======================= CSR build =======================
__global__ void count_deg_k(const int* __restrict__ dst, int* __restrict__ deg) {
    int e = blockIdx.x * blockDim.x + threadIdx.x;
    if (e < N_EDGES) atomicAdd(&deg[dst[e]], 1);
}

__global__ void scan_csr_k(const int* __restrict__ deg, int* __restrict__ rowptr,
                           int* __restrict__ cursor) {
    __shared__ int warpS[32];
    __shared__ int warpOff[32];
    __shared__ int carryS;
    int tid = threadIdx.x, lane = tid & 31, w = tid >> 5;
    if (tid == 0) { carryS = 0; rowptr[0] = 0; }
    __syncthreads();
    for (int base = 0; base < N_NODES; base += 1024) {
        int i = base + tid;
        int v = (i < N_NODES) ? deg[i] : 0;
        int x = v;
        #pragma unroll
        for (int o = 1; o < 32; o <<= 1) {
            int t = __shfl_up_sync(0xFFFFFFFFu, x, o);
            if (lane >= o) x += t;
        }
        if (lane == 31) warpS[w] = x;
        __syncthreads();
        if (w == 0) {
            int y = warpS[lane];
            int z = y;
            #pragma unroll
            for (int o = 1; o < 32; o <<= 1) {
                int t = __shfl_up_sync(0xFFFFFFFFu, z, o);
                if (lane >= o) z += t;
            }
            warpOff[lane] = z - y;
            if (lane == 31) warpS[0] = z;
        }
        __syncthreads();
        int c = carryS;
        int incl = x + warpOff[w];
        if (i < N_NODES) {
            rowptr[i + 1] = c + incl;
            cursor[i] = c + incl - v;
        }
        int chunkTot = warpS[0];
        __syncthreads();
        if (tid == 0) carryS = c + chunkTot;
        __syncthreads();
    }
}

__global__ void fill_csr_k(const int* __restrict__ src, const int* __restrict__ dst,
                           const float* __restrict__ ea, int* __restrict__ cursor,
                           int* __restrict__ srcp, float4* __restrict__ eap) {
    int e = blockIdx.x * blockDim.x + threadIdx.x;
    if (e < N_EDGES) {
        int p = atomicAdd(&cursor[dst[e]], 1);
        srcp[p] = src[e];
        float4 t;
        t.x = ea[(size_t)e * 3];
        t.y = ea[(size_t)e * 3 + 1];
        t.z = ea[(size_t)e * 3 + 2];
        t.w = 0.f;
        eap[p] = t;
    }
}

// ======================= aggregation =======================
__global__ void aggregate11_k(const float* __restrict__ h, const float4* __restrict__ eap,
                              const float* __restrict__ ew, const float* __restrict__ eb,
                              const float* __restrict__ epsp,
                              const int* __restrict__ srcp, const int* __restrict__ rowptr,
                              float* __restrict__ out) {
    int n = blockIdx.x * 4 + (threadIdx.x >> 5);
    int d = threadIdx.x & 31;
    if (n >= N_NODES || d >= IN_DIM) return;
    float w0 = ew[d], w1 = ew[IN_DIM + d], w2 = ew[2 * IN_DIM + d], b = eb[d];
    int s0 = rowptr[n], s1 = rowptr[n + 1];
    float acc = 0.f;
    int p = s0;
    for (; p + 2 <= s1; p += 2) {
        int i0 = srcp[p], i1 = srcp[p + 1];
        float4 e0 = eap[p], e1 = eap[p + 1];
        float gg0 = h[(size_t)i0 * IN_DIM + d];
        float gg1 = h[(size_t)i1 * IN_DIM + d];
        acc += fmaxf(gg0 + e0.x * w0 + e0.y * w1 + e0.z * w2 + b, 0.f);
        acc += fmaxf(gg1 + e1.x * w0 + e1.y * w1 + e1.z * w2 + b, 0.f);
    }
    for (; p < s1; p++) {
        int i0 = srcp[p];
        float4 e0 = eap[p];
        acc += fmaxf(h[(size_t)i0 * IN_DIM + d] + e0.x * w0 + e0.y * w1 + e0.z * w2 + b, 0.f);
    }
    float eps = *epsp;
    out[(size_t)n * IN_DIM + d] = (1.f + eps) * h[(size_t)n * IN_DIM + d] + acc;
}

// warp-per-node, float4-per-lane (lane owns dims 4*lane..4*lane+3)
__global__ void __launch_bounds__(256)
aggregate128_k(const float4* __restrict__ h4, const float4* __restrict__ eap,
               const float* __restrict__ ew, const float* __restrict__ eb,
               const float* __restrict__ epsp,
               const int* __restrict__ srcp, const int* __restrict__ rowptr,
               float4* __restrict__ out4) {
    int n = blockIdx.x * 8 + (threadIdx.x >> 5);
    int lane = threadIdx.x & 31;
    if (n >= N_NODES) return;
    float4 w0 = __ldg((const float4*)ew + lane);
    float4 w1 = __ldg((const float4*)(ew + HID) + lane);
    float4 w2 = __ldg((const float4*)(ew + 2 * HID) + lane);
    float4 bb = __ldg((const float4*)eb + lane);
    int s0 = rowptr[n], s1 = rowptr[n + 1];
    float ax = 0.f, ay = 0.f, az = 0.f, aw = 0.f;
    int p = s0;
    for (; p + 4 <= s1; p += 4) {
        int i0 = __ldg(srcp + p), i1 = __ldg(srcp + p + 1);
        int i2 = __ldg(srcp + p + 2), i3 = __ldg(srcp + p + 3);
        float4 e0 = __ldg(eap + p), e1 = __ldg(eap + p + 1);
        float4 e2 = __ldg(eap + p + 2), e3 = __ldg(eap + p + 3);
        float4 g0 = __ldg(h4 + (size_t)i0 * 32 + lane);
        float4 g1 = __ldg(h4 + (size_t)i1 * 32 + lane);
        float4 g2 = __ldg(h4 + (size_t)i2 * 32 + lane);
        float4 g3 = __ldg(h4 + (size_t)i3 * 32 + lane);
        float c0 = e0.x * w0.x + e0.y * w1.x + e0.z * w2.x + bb.x;
        float c1 = e0.x * w0.y + e0.y * w1.y + e0.z * w2.y + bb.y;
        float c2 = e0.x * w0.z + e0.y * w1.z + e0.z * w2.z + bb.z;
        float c3 = e0.x * w0.w + e0.y * w1.w + e0.z * w2.w + bb.w;
        ax += fmaxf(g0.x + c0, 0.f); ay += fmaxf(g0.y + c1, 0.f);
        az += fmaxf(g0.z + c2, 0.f); aw += fmaxf(g0.w + c3, 0.f);
        c0 = e1.x * w0.x + e1.y * w1.x + e1.z * w2.x + bb.x;
        c1 = e1.x * w0.y + e1.y * w1.y + e1.z * w2.y + bb.y;
        c2 = e1.x * w0.z + e1.y * w1.z + e1.z * w2.z + bb.z;
        c3 = e1.x * w0.w + e1.y * w1.w + e1.z * w2.w + bb.w;
        ax += fmaxf(g1.x + c0, 0.f); ay += fmaxf(g1.y + c1, 0.f);
        az += fmaxf(g1.z + c2, 0.f); aw += fmaxf(g1.w + c3, 0.f);
        c0 = e2.x * w0.x + e2.y * w1.x + e2.z * w2.x + bb.x;
        c1 = e2.x * w0.y + e2.y * w1.y + e2.z * w2.y + bb.y;
        c2 = e2.x * w0.z + e2.y * w1.z + e2.z * w2.z + bb.z;
        c3 = e2.x * w0.w + e2.y * w1.w + e2.z * w2.w + bb.w;
        ax += fmaxf(g2.x + c0, 0.f); ay += fmaxf(g2.y + c1, 0.f);
        az += fmaxf(g2.z + c2, 0.f); aw += fmaxf(g2.w + c3, 0.f);
        c0 = e3.x * w0.x + e3.y * w1.x + e3.z * w2.x + bb.x;
        c1 = e3.x * w0.y + e3.y * w1.y + e3.z * w2.y + bb.y;
        c2 = e3.x * w0.z + e3.y * w1.z + e3.z * w2.z + bb.z;
        c3 = e3.x * w0.w + e3.y * w1.w + e3.z * w2.w + bb.w;
        ax += fmaxf(g3.x + c0, 0.f); ay += fmaxf(g3.y + c1, 0.f);
        az += fmaxf(g3.z + c2, 0.f); aw += fmaxf(g3.w + c3, 0.f);
    }
    for (; p < s1; p++) {
        int i0 = __ldg(srcp + p);
        float4 e0 = __ldg(eap + p);
        float4 g0 = __ldg(h4 + (size_t)i0 * 32 + lane);
        ax += fmaxf(g0.x + e0.x * w0.x + e0.y * w1.x + e0.z * w2.x + bb.x, 0.f);
        ay += fmaxf(g0.y + e0.x * w0.y + e0.y * w1.y + e0.z * w2.y + bb.y, 0.f);
        az += fmaxf(g0.z + e0.x * w0.z + e0.y * w1.z + e0.z * w2.z + bb.z, 0.f);
        aw += fmaxf(g0.w + e0.x * w0.w + e0.y * w1.w + e0.z * w2.w + bb.w, 0.f);
    }
    float eps1 = 1.f + *epsp;
    float4 hn = __ldg(h4 + (size_t)n * 32 + lane);
    float4 o;
    o.x = eps1 * hn.x + ax;
    o.y = eps1 * hn.y + ay;
    o.z = eps1 * hn.z + az;
    o.w = eps1 * hn.w + aw;
    out4[(size_t)n * 32 + lane] = o;
}

// ======================= fused 2-GEMM MLP (fp16 2-pass, M=64 tiles, 3 CTAs/SM) =======================
#define APAD 136
#define SX_HI   0
#define SX_LO   17408
#define SY      34816
#define S_B1    69632
#define S_B2    70144
#define S_STAT  70656
#define SM_TOTAL (S_STAT + 2048)
#define STG_PITCH 130

__global__ void __launch_bounds__(256, 3)
gemm_mlp_k(const float* __restrict__ A, int M, int Kact, int Apitch,
           const __half* __restrict__ W1, const float* __restrict__ b1,
           const __half* __restrict__ W2, const float* __restrict__ b2,
           float* __restrict__ C, int do_relu2,
           float* __restrict__ ssum, float* __restrict__ ssq, int nsteps1) {
    extern __shared__ __align__(16) char smem[];
    __half* aHi = (__half*)(smem + SX_HI);
    __half* aLo = (__half*)(smem + SX_LO);
    __half* wS  = (__half*)(smem + SY);
    float* b1S = (float*)(smem + S_B1);
    float* b2S = (float*)(smem + S_B2);
    float* statS = (float*)(smem + S_STAT);

    int tid = threadIdx.x;
    int lane = tid & 31;
    int wid = tid >> 5;
    int rowBase = blockIdx.x * 64;
    int kmax1 = nsteps1 << 4;

    if (tid < HID) { b1S[tid] = b1[tid]; b2S[tid] = b2[tid]; }

    // ---- load + split A [64 x kmax1] into fp16 hi/lo ----
    if (Kact == HID) {
        for (int idx = tid; idx < 64 * 32; idx += 256) {
            int r = idx >> 5, seg = idx & 31;
            int gr = rowBase + r;
            float4 v = (gr < M) ? __ldg((const float4*)(A + (size_t)gr * Apitch) + seg)
                                : make_float4(0.f, 0.f, 0.f, 0.f);
            __half h0 = __float2half_rn(v.x), h1 = __float2half_rn(v.y);
            __half h2 = __float2half_rn(v.z), h3 = __float2half_rn(v.w);
            __half l0 = __float2half_rn(v.x - __half2float(h0));
            __half l1 = __float2half_rn(v.y - __half2float(h1));
            __half l2 = __float2half_rn(v.z - __half2float(h2));
            __half l3 = __float2half_rn(v.w - __half2float(h3));
            __half2* ph = (__half2*)&aHi[r * APAD + seg * 4];
            __half2* pl = (__half2*)&aLo[r * APAD + seg * 4];
            ph[0] = __halves2half2(h0, h1); ph[1] = __halves2half2(h2, h3);
            pl[0] = __halves2half2(l0, l1); pl[1] = __halves2half2(l2, l3);
        }
    } else {
        for (int idx = tid; idx < 64 * 16; idx += 256) {
            int r = idx >> 4, k = idx & 15;
            int gr = rowBase + r;
            float a = (gr < M && k < Kact) ? __ldg(A + (size_t)gr * Apitch + k) : 0.f;
            __half h = __float2half_rn(a);
            aHi[r * APAD + k] = h;
            aLo[r * APAD + k] = __float2half_rn(a - __half2float(h));
        }
    }
    for (int idx = tid; idx < kmax1 * 16; idx += 256) {
        int k = idx >> 4, seg = idx & 15;
        *(uint4*)&wS[k * APAD + seg * 8] = __ldg((const uint4*)(W1 + k * HID) + seg);
    }
    __syncthreads();

    int warpR = (wid >> 2) << 5;
    int warpC = (wid & 3) << 5;
    uint32_t aBase = smem_u32(aHi);
    uint32_t wBase = smem_u32(wS);
    float acc[2][4][4];

    #pragma unroll
    for (int m = 0; m < 2; m++)
        #pragma unroll
        for (int j = 0; j < 4; j++)
            #pragma unroll
            for (int q = 0; q < 4; q++) acc[m][j][q] = 0.f;

    // ================= pass 1 =================
    for (int s = 0; s < nsteps1; s++) {
        int k0 = s << 4;
        uint32_t aAddr = aBase +
            ((uint32_t)((warpR + (lane & 15)) * APAD + k0 + ((lane >> 4) << 3)) << 1);
        uint32_t ah0[4], ah1[4], al0[4], al1[4];
        LDSM_X4(ah0[0], ah0[1], ah0[2], ah0[3], aAddr);
        LDSM_X4(ah1[0], ah1[1], ah1[2], ah1[3], aAddr + 16 * APAD * 2);
        LDSM_X4(al0[0], al0[1], al0[2], al0[3], aAddr + (SX_LO - SX_HI));
        LDSM_X4(al1[0], al1[1], al1[2], al1[3], aAddr + (SX_LO - SX_HI) + 16 * APAD * 2);

        uint32_t bAddr = wBase +
            ((uint32_t)((k0 + (lane & 7) + ((lane >> 3) & 1) * 8) * APAD +
                        warpC + ((lane >> 4) << 3)) << 1);
        uint32_t bf[4][2];
        #pragma unroll
        for (int pp = 0; pp < 2; pp++) {
            uint32_t r0, r1, r2, r3;
            LDSM_X4T(r0, r1, r2, r3, bAddr + pp * 32);
            bf[2 * pp][0] = r0; bf[2 * pp][1] = r1;
            bf[2 * pp + 1][0] = r2; bf[2 * pp + 1][1] = r3;
        }
        #pragma unroll
        for (int j = 0; j < 4; j++) {
            mma_fp16(acc[0][j], ah0, bf[j]);
            mma_fp16(acc[1][j], ah1, bf[j]);
            mma_fp16(acc[0][j], al0, bf[j]);
            mma_fp16(acc[1][j], al1, bf[j]);
        }
    }
    __syncthreads();

    // ---- T1 = relu(acc + b1) -> split into X region; load W2 into Y ----
    #pragma unroll
    for (int m = 0; m < 2; m++) {
        #pragma unroll
        for (int j = 0; j < 4; j++) {
            #pragma unroll
            for (int q = 0; q < 4; q++) {
                int row = warpR + m * 16 + (lane >> 2) + ((q >> 1) << 3);
                int col = warpC + j * 8 + ((lane & 3) << 1) + (q & 1);
                float t = fmaxf(acc[m][j][q] + b1S[col], 0.f);
                __half h = __float2half_rn(t);
                aHi[row * APAD + col] = h;
                aLo[row * APAD + col] = __float2half_rn(t - __half2float(h));
            }
        }
    }
    for (int idx = tid; idx < 128 * 16; idx += 256) {
        int k = idx >> 4, seg = idx & 15;
        *(uint4*)&wS[k * APAD + seg * 8] = __ldg((const uint4*)(W2 + k * HID) + seg);
    }
    __syncthreads();

    // ================= pass 2 (K = 128) =================
    #pragma unroll
    for (int m = 0; m < 2; m++)
        #pragma unroll
        for (int j = 0; j < 4; j++)
            #pragma unroll
            for (int q = 0; q < 4; q++) acc[m][j][q] = 0.f;

    for (int s = 0; s < 8; s++) {
        int k0 = s << 4;
        uint32_t aAddr = aBase +
            ((uint32_t)((warpR + (lane & 15)) * APAD + k0 + ((lane >> 4) << 3)) << 1);
        uint32_t ah0[4], ah1[4], al0[4], al1[4];
        LDSM_X4(ah0[0], ah0[1], ah0[2], ah0[3], aAddr);
        LDSM_X4(ah1[0], ah1[1], ah1[2], ah1[3], aAddr + 16 * APAD * 2);
        LDSM_X4(al0[0], al0[1], al0[2], al0[3], aAddr + (SX_LO - SX_HI));
        LDSM_X4(al1[0], al1[1], al1[2], al1[3], aAddr + (SX_LO - SX_HI) + 16 * APAD * 2);

        uint32_t bAddr = wBase +
            ((uint32_t)((k0 + (lane & 7) + ((lane >> 3) & 1) * 8) * APAD +
                        warpC + ((lane >> 4) << 3)) << 1);
        uint32_t bf[4][2];
        #pragma unroll
        for (int pp = 0; pp < 2; pp++) {
            uint32_t r0, r1, r2, r3;
            LDSM_X4T(r0, r1, r2, r3, bAddr + pp * 32);
            bf[2 * pp][0] = r0; bf[2 * pp][1] = r1;
            bf[2 * pp + 1][0] = r2; bf[2 * pp + 1][1] = r3;
        }
        #pragma unroll
        for (int j = 0; j < 4; j++) {
            mma_fp16(acc[0][j], ah0, bf[j]);
            mma_fp16(acc[1][j], ah1, bf[j]);
            mma_fp16(acc[0][j], al0, bf[j]);
            mma_fp16(acc[1][j], al1, bf[j]);
        }
    }
    __syncthreads();

    // ---- epilogue: stage to smem (reuse X region) ----
    float* stg = (float*)smem;
    #pragma unroll
    for (int m = 0; m < 2; m++) {
        #pragma unroll
        for (int j = 0; j < 4; j++) {
            int row = warpR + m * 16 + (lane >> 2);
            int col = warpC + j * 8 + ((lane & 3) << 1);
            stg[row * STG_PITCH + col]       = acc[m][j][0];
            stg[row * STG_PITCH + col + 1]   = acc[m][j][1];
            stg[(row + 8) * STG_PITCH + col]     = acc[m][j][2];
            stg[(row + 8) * STG_PITCH + col + 1] = acc[m][j][3];
        }
    }
    __syncthreads();

    // ---- coalesced store + bias2/relu2 + fused BN stats ----
    {
        int c = tid & 127, hh = tid >> 7;
        float bia = b2S[c];
        float s0 = 0.f, q0 = 0.f;
        #pragma unroll 4
        for (int j = 0; j < 32; j++) {
            int r = hh * 32 + j;
            int gr = rowBase + r;
            if (gr < M) {
                float v = stg[r * STG_PITCH + c] + bia;
                if (do_relu2) v = fmaxf(v, 0.f);
                C[(size_t)gr * HID + c] = v;
                s0 += v;
                q0 += v * v;
            }
        }
        if (ssum) {
            statS[hh * 128 + c] = s0;
            statS[256 + hh * 128 + c] = q0;
            __syncthreads();
            if (tid < 128) {
                atomicAdd(&ssum[tid], statS[tid] + statS[128 + tid]);
                atomicAdd(&ssq[tid], statS[256 + tid] + statS[384 + tid]);
            }
        }
    }
}

// ======================= BN + relu + optional residual (float4) =======================
__global__ void bn_relu_res_k(const float4* __restrict__ tmp, const float* __restrict__ stats,
                              const float* __restrict__ gamma, const float* __restrict__ beta,
                              const float4* __restrict__ res, float4* __restrict__ out,
                              int n_rows) {
    size_t i = (size_t)blockIdx.x * blockDim.x + threadIdx.x;
    size_t total = (size_t)n_rows * 32;
    if (i >= total) return;
    int d = ((int)(i & 31)) << 2;
    float invN = 1.f / (float)n_rows;
    float4 t = tmp[i];
    float4 o;
    {
        float mu = stats[d] * invN;
        float var = stats[HID + d] * invN - mu * mu;
        o.x = fmaxf((t.x - mu) * rsqrtf(var + BN_EPS) * gamma[d] + beta[d], 0.f);
    }
    {
        float mu = stats[d + 1] * invN;
        float var = stats[HID + d + 1] * invN - mu * mu;
        o.y = fmaxf((t.y - mu) * rsqrtf(var + BN_EPS) * gamma[d + 1] + beta[d + 1], 0.f);
    }
    {
        float mu = stats[d + 2] * invN;
        float var = stats[HID + d + 2] * invN - mu * mu;
        o.z = fmaxf((t.z - mu) * rsqrtf(var + BN_EPS) * gamma[d + 2] + beta[d + 2], 0.f);
    }
    {
        float mu = stats[d + 3] * invN;
        float var = stats[HID + d + 3] * invN - mu * mu;
        o.w = fmaxf((t.w - mu) * rsqrtf(var + BN_EPS) * gamma[d + 3] + beta[d + 3], 0.f);
    }
    if (res) {
        float4 r = res[i];
        o.x += r.x; o.y += r.y; o.z += r.z; o.w += r.w;
    }
    out[i] = o;
}

// ======================= pooling =======================
__global__ void graph_ptr_k(const int* __restrict__ batch, int* __restrict__ gptr) {
    int g = blockIdx.x * blockDim.x + threadIdx.x;
    if (g > N_GRAPHS) return;
    int lo = 0, hi = N_NODES;
    while (lo < hi) {
        int mid = (lo + hi) >> 1;
        if (batch[mid] < g) lo = mid + 1; else hi = mid;
    }
    gptr[g] = lo;
}
__global__ void pool_k(const float* __restrict__ h, const int* __restrict__ gptr,
                       float* __restrict__ pooled) {
    int g = blockIdx.x;
    int d = threadIdx.x;
    int a = gptr[g], b = gptr[g + 1];
    float acc = 0.f;
    for (int n = a; n < b; n++) acc += h[(size_t)n * HID + d];
    int cnt = b - a;
    float c = (float)(cnt > 1 ? cnt : 1);
    pooled[(size_t)g * HID + d] = acc / c;
}

// ======================= head final dot =======================
__global__ void head_out_k(const float* __restrict__ z, const float* __restrict__ w,
                           const float* __restrict__ b, float* __restrict__ out) {
    int g = blockIdx.x;
    int t = threadIdx.x; // 128
    float v = z[(size_t)g * HID + t] * w[t];
    #pragma unroll
    for (int off = 16; off; off >>= 1) v += __shfl_down_sync(0xFFFFFFFFu, v, off);
    __shared__ float s[4];
    if ((t & 31) == 0) s[t >> 5] = v;
    __syncthreads();
    if (t == 0) out[g] = s[0] + s[1] + s[2] + s[3] + b[0];
}

// ======================= host =======================
static void* sym_addr(const void* sym) {
    void* p = nullptr;
    cudaGetSymbolAddress(&p, sym);
    return p;
}

extern "C" void kernel_launch(void* const* d_in, const int* in_sizes, int n_in,
                              void* d_out, int out_size) {
    const float* x        = (const float*)d_in[0];
    const float* edge_attr= (const float*)d_in[1];
    const float* e_w0     = (const float*)d_in[2];
    const float* e_b0     = (const float*)d_in[3];
    const float* w1_0     = (const float*)d_in[4];
    const float* b1_0     = (const float*)d_in[5];
    const float* w2_0     = (const float*)d_in[6];
    const float* b2_0     = (const float*)d_in[7];
    const float* gamma0   = (const float*)d_in[8];
    const float* beta0    = (const float*)d_in[9];
    const float* eps0     = (const float*)d_in[10];
    const float* e_w      = (const float*)d_in[11];
    const float* e_b      = (const float*)d_in[12];
    const float* w1       = (const float*)d_in[13];
    const float* b1       = (const float*)d_in[14];
    const float* w2       = (const float*)d_in[15];
    const float* b2       = (const float*)d_in[16];
    const float* gamma    = (const float*)d_in[17];
    const float* beta     = (const float*)d_in[18];
    const float* eps_r    = (const float*)d_in[19];
    const float* hw1      = (const float*)d_in[20];
    const float* hb1      = (const float*)d_in[21];
    const float* hw2      = (const float*)d_in[22];
    const float* hb2      = (const float*)d_in[23];
    const float* hw3      = (const float*)d_in[24];
    const float* hb3      = (const float*)d_in[25];
    const int*   edge_index = (const int*)d_in[26];
    const int*   batch    = (const int*)d_in[27];

    const int* src = edge_index;
    const int* dst = edge_index + N_EDGES;

    float* pre   = (float*)sym_addr(g_pre);
    float* tmp   = (float*)sym_addr(g_tmp);
    float* hA    = (float*)sym_addr(g_hA);
    float* hB    = (float*)sym_addr(g_hB);
    int*   deg   = (int*)sym_addr(g_deg);
    int*   rowptr= (int*)sym_addr(g_rowptr);
    int*   cursor= (int*)sym_addr(g_cursor);
    int*   srcp  = (int*)sym_addr(g_srcp);
    float4* eap  = (float4*)sym_addr(g_eap);
    int*   gptr  = (int*)sym_addr(g_gptr);
    float* stats = (float*)sym_addr(g_stats);
    float* pool  = (float*)sym_addr(g_pool);
    float* z2    = (float*)sym_addr(g_z2);
    __half* wh   = (__half*)sym_addr(g_wh);
    float* out   = (float*)d_out;

    cudaFuncSetAttribute(gemm_mlp_k, cudaFuncAttributeMaxDynamicSharedMemorySize, SM_TOTAL);

    const int SLOT = 128 * 128;

    init_k<<<(12 * 16384 + 255) / 256, 256>>>(w1_0, w2_0, w1, w2, hw1, hw2, wh, deg, stats);
    count_deg_k<<<(N_EDGES + 255) / 256, 256>>>(dst, deg);
    scan_csr_k<<<1, 1024>>>(deg, rowptr, cursor);
    fill_csr_k<<<(N_EDGES + 255) / 256, 256>>>(src, dst, edge_attr, cursor, srcp, eap);

    const int GB_N = (N_NODES + 63) / 64;
    const int GB_G = (N_GRAPHS + 63) / 64;
    const int BN_BLOCKS = (int)(((size_t)N_NODES * 32 + 255) / 256);

    aggregate11_k<<<(N_NODES + 3) / 4, 128>>>(x, eap, e_w0, e_b0, eps0, srcp, rowptr, pre);
    gemm_mlp_k<<<GB_N, 256, SM_TOTAL>>>(pre, N_NODES, IN_DIM, IN_DIM,
                                        wh + 0 * SLOT, b1_0,
                                        wh + 1 * SLOT, b2_0,
                                        tmp, 0, stats, stats + HID, 1);
    bn_relu_res_k<<<BN_BLOCKS, 256>>>((const float4*)tmp, stats, gamma0, beta0,
                                      nullptr, (float4*)hA, N_NODES);

    float* cur = hA;
    float* nxt = hB;
    for (int i = 0; i < N_REST; i++) {
        float* st = stats + (size_t)(1 + i) * 2 * HID;
        aggregate128_k<<<(N_NODES + 7) / 8, 256>>>((const float4*)cur, eap,
                                                   e_w + (size_t)i * 3 * HID,
                                                   e_b + (size_t)i * HID, eps_r + i,
                                                   srcp, rowptr, (float4*)pre);
        gemm_mlp_k<<<GB_N, 256, SM_TOTAL>>>(pre, N_NODES, HID, HID,
                                            wh + (2 + i) * SLOT, b1 + (size_t)i * HID,
                                            wh + (6 + i) * SLOT, b2 + (size_t)i * HID,
                                            tmp, 0, st, st + HID, 8);
        bn_relu_res_k<<<BN_BLOCKS, 256>>>((const float4*)tmp, st,
                                          gamma + (size_t)i * HID, beta + (size_t)i * HID,
                                          (const float4*)cur, (float4*)nxt, N_NODES);
        float* t = cur; cur = nxt; nxt = t;
    }

    graph_ptr_k<<<(N_GRAPHS + 1 + 127) / 128, 128>>>(batch, gptr);
    pool_k<<<N_GRAPHS, HID>>>(cur, gptr, pool);

    gemm_mlp_k<<<GB_G, 256, SM_TOTAL>>>(pool, N_GRAPHS, HID, HID,
                                        wh + 10 * SLOT, hb1,
                                        wh + 11 * SLOT, hb2,
                                        z2, 1, nullptr, nullptr, 8);
    head_out_k<<<N_GRAPHS, HID>>>(z2, hw3, hb3, out);
}